// round 7
// baseline (speedup 1.0000x reference)
#include <cuda_runtime.h>
#include <cuda_bf16.h>
#include <cstdint>

// C = triu(triu(A) @ triu(B)), N = 4096, fp32.
// sm_103a path: A,B pre-split into masked bf16 hi/lo (B transposed K-major);
// main kernel: 4-stage cp.async -> tcgen05 pipeline, KC=32 (SW64 64B rows),
// 3 bf16 MMAs per K16 (h*h + h*l + l*h), fp32 accum in TMEM, 128x256 tiles,
// SPLIT-K: k-range split into <=32-chunk segments across CTAs; multi-segment
// tiles write fp32 partials into slabs, summed by a reduce kernel.
// Fallback (arch-generic PTX): SIMT fp32 kernel with the same segmentation.

constexpr int NMAT = 4096;
constexpr int BM = 128;
constexpr int BN = 256;
constexpr int KC = 32;         // k-chunk (32 bf16 = 64B rows, SW64 native)
constexpr int THREADS = 256;
constexpr int STAGES = 4;
constexpr int SEG = 32;        // max chunks per split-K segment
constexpr int MAXSEG = 4;      // ceil(128 / SEG)

// Scratch: masked splits. gA0/gA1: A [r][k]. gB0/gB1: B^T [c][k]. All K-major.
__device__ __align__(1024) __nv_bfloat16 gA0[(size_t)NMAT * NMAT];
__device__ __align__(1024) __nv_bfloat16 gA1[(size_t)NMAT * NMAT];
__device__ __align__(1024) __nv_bfloat16 gB0[(size_t)NMAT * NMAT];
__device__ __align__(1024) __nv_bfloat16 gB1[(size_t)NMAT * NMAT];
// Split-K partial slabs (fp32), one full matrix per segment index.
__device__ __align__(1024) float gPart[(size_t)MAXSEG * NMAT * NMAT];

// ---------------------------------------------------------------- helpers
__device__ __forceinline__ uint32_t smem_u32(const void* p) {
    uint32_t a;
    asm("{ .reg .u64 t; cvta.to.shared.u64 t, %1; cvt.u32.u64 %0, t; }"
        : "=r"(a) : "l"(p));
    return a;
}

#if defined(__CUDA_ARCH_FEAT_SM103_ALL) || !defined(__CUDA_ARCH__)
__device__ __forceinline__ uint32_t elect_one() {
    uint32_t p;
    asm volatile("{ .reg .pred p; elect.sync _|p, 0xFFFFFFFF; selp.b32 %0,1,0,p; }"
                 : "=r"(p));
    return p;
}
__device__ __forceinline__ void mma_f16_ss(uint32_t d, uint64_t ad, uint64_t bd,
                                           uint32_t idesc, uint32_t en) {
    asm volatile(
        "{\n\t.reg .pred p;\n\tsetp.ne.u32 p, %5, 0;\n\t"
        "tcgen05.mma.cta_group::1.kind::f16 [%0], %1, %2, %3, {%4,%4,%4,%4}, p;\n\t}"
        :: "r"(d), "l"(ad), "l"(bd), "r"(idesc), "r"(0u), "r"(en) : "memory");
}
__device__ __forceinline__ void cp_async16(uint32_t dst, const void* src) {
    asm volatile("cp.async.cg.shared.global [%0], [%1], 16;"
                 :: "r"(dst), "l"(src) : "memory");
}
#define CP_COMMIT()      asm volatile("cp.async.commit_group;" ::: "memory")
#define CP_WAIT0()       asm volatile("cp.async.wait_group 0;" ::: "memory")
#define CP_WAIT1()       asm volatile("cp.async.wait_group 1;" ::: "memory")
#define CP_WAIT2()       asm volatile("cp.async.wait_group 2;" ::: "memory")
#define TC_ALLOC(sl, n)  asm volatile("tcgen05.alloc.cta_group::1.sync.aligned.shared::cta.b32 [%0], %1;" :: "r"(sl), "r"((uint32_t)(n)) : "memory")
#define TC_RELINQ()      asm volatile("tcgen05.relinquish_alloc_permit.cta_group::1.sync.aligned;")
#define TC_DEALLOC(t, n) asm volatile("tcgen05.dealloc.cta_group::1.sync.aligned.b32 %0, %1;" :: "r"(t), "r"((uint32_t)(n)))
#define TC_COMMIT(mb)    asm volatile("tcgen05.commit.cta_group::1.mbarrier::arrive::one.shared::cluster.b64 [%0];" :: "r"(mb) : "memory")
#define TC_FENCE_AFTER() asm volatile("tcgen05.fence::after_thread_sync;" ::: "memory")
#define TC_FENCE_BEFORE() asm volatile("tcgen05.fence::before_thread_sync;" ::: "memory")
#define TC_WAIT_LD()     asm volatile("tcgen05.wait::ld.sync.aligned;" ::: "memory")
#define FENCE_ASYNC()    asm volatile("fence.proxy.async.shared::cta;" ::: "memory")
#define MBAR_INIT(mb, c) asm volatile("mbarrier.init.shared.b64 [%0], %1;" :: "r"(mb), "r"((uint32_t)(c)) : "memory")

#define MBAR_WAIT_PARITY(mb, ph) do {                                           \
    uint32_t _m = (mb), _p = (ph), _d;                                          \
    asm volatile("{\n\t.reg .pred p;\n\t"                                       \
        "mbarrier.try_wait.parity.acquire.cta.shared::cta.b64 p, [%1], %2;\n\t" \
        "selp.b32 %0, 1, 0, p;\n\t}" : "=r"(_d) : "r"(_m), "r"(_p) : "memory"); \
    if (!_d) {                                                                  \
        asm volatile("{\n\t.reg .pred P1;\n\t"                                  \
        "WL_%=:\n\t"                                                            \
        "mbarrier.try_wait.parity.acquire.cta.shared::cta.b64 P1, [%0], %1, 0x989680;\n\t" \
        "@P1 bra.uni WD_%=;\n\t"                                                \
        "bra.uni WL_%=;\n\t"                                                    \
        "WD_%=:\n\t}" :: "r"(_m), "r"(_p) : "memory");                          \
    }                                                                           \
} while (0)

#define LDTM_X32(r, a)                                                          \
    asm volatile("tcgen05.ld.sync.aligned.32x32b.x32.b32 "                      \
        "{%0, %1, %2, %3, %4, %5, %6, %7, %8, %9, %10, %11, %12, %13, %14, %15,"\
        " %16, %17, %18, %19, %20, %21, %22, %23, %24, %25, %26, %27, %28, %29, %30, %31}, [%32];" \
        : "=r"((r)[0]), "=r"((r)[1]), "=r"((r)[2]), "=r"((r)[3]),               \
          "=r"((r)[4]), "=r"((r)[5]), "=r"((r)[6]), "=r"((r)[7]),               \
          "=r"((r)[8]), "=r"((r)[9]), "=r"((r)[10]), "=r"((r)[11]),             \
          "=r"((r)[12]), "=r"((r)[13]), "=r"((r)[14]), "=r"((r)[15]),           \
          "=r"((r)[16]), "=r"((r)[17]), "=r"((r)[18]), "=r"((r)[19]),           \
          "=r"((r)[20]), "=r"((r)[21]), "=r"((r)[22]), "=r"((r)[23]),           \
          "=r"((r)[24]), "=r"((r)[25]), "=r"((r)[26]), "=r"((r)[27]),           \
          "=r"((r)[28]), "=r"((r)[29]), "=r"((r)[30]), "=r"((r)[31])            \
        : "r"(a))
#endif  // tcgen05 helpers

// SW64 smem descriptor (K-major, 64B rows): layout=SW64(4), ver=1, SBO=32, LBO=1
constexpr uint64_t DESC_BASE_SW64 =
    (uint64_t(4) << 61) | (uint64_t(1) << 46) | (uint64_t(32) << 32) | (uint64_t(1) << 16);
__device__ __forceinline__ uint64_t mk_desc64(uint32_t a) {
    return DESC_BASE_SW64 | ((uint64_t)(a >> 4) & 0x3FFF);
}

__device__ __forceinline__ uint32_t pack_bf16x2(float a, float b) {
    __nv_bfloat162 h = __halves2bfloat162(__float2bfloat16(a), __float2bfloat16(b));
    return *reinterpret_cast<uint32_t*>(&h);
}

// ---------------------------------------------------------------- pre-pass
// z=0: gA0/gA1[r][k] = hi/lo bf16 of (k>=r ? A[r][k] : 0)   (row-major copy)
// z=1: gB0/gB1[c][k] = hi/lo bf16 of (k<=c ? B[k][c] : 0)   (transpose)
// Regions never read by the main kernel are skipped entirely.
__global__ __launch_bounds__(256)
void split_ab_kernel(const float* __restrict__ A, const float* __restrict__ B) {
    const int tid = threadIdx.x;

    if (blockIdx.z == 0) {
        const int rb = blockIdx.y * 64, kb = blockIdx.x * 64;
        if (kb < (rb & ~127)) return;            // k < row0 of main tile: unread
        const int r = rb + (tid >> 2);
        const int k0 = kb + (tid & 3) * 16;
        uint32_t hw[8], lw[8];
        if (kb + 63 < rb) {                       // read, but fully masked
            #pragma unroll
            for (int i = 0; i < 8; ++i) { hw[i] = 0u; lw[i] = 0u; }
        } else {
            #pragma unroll
            for (int q = 0; q < 4; ++q) {
                float4 v = *reinterpret_cast<const float4*>(
                    A + (size_t)r * NMAT + k0 + q * 4);
                const int kg = k0 + q * 4;
                float x0 = (kg + 0 >= r) ? v.x : 0.f;
                float x1 = (kg + 1 >= r) ? v.y : 0.f;
                float x2 = (kg + 2 >= r) ? v.z : 0.f;
                float x3 = (kg + 3 >= r) ? v.w : 0.f;
                float h0 = __bfloat162float(__float2bfloat16(x0));
                float h1 = __bfloat162float(__float2bfloat16(x1));
                float h2 = __bfloat162float(__float2bfloat16(x2));
                float h3 = __bfloat162float(__float2bfloat16(x3));
                hw[2 * q + 0] = pack_bf16x2(x0, x1);
                hw[2 * q + 1] = pack_bf16x2(x2, x3);
                lw[2 * q + 0] = pack_bf16x2(x0 - h0, x1 - h1);
                lw[2 * q + 1] = pack_bf16x2(x2 - h2, x3 - h3);
            }
        }
        uint4* p0 = reinterpret_cast<uint4*>(gA0 + (size_t)r * NMAT + k0);
        uint4* p1 = reinterpret_cast<uint4*>(gA1 + (size_t)r * NMAT + k0);
        p0[0] = make_uint4(hw[0], hw[1], hw[2], hw[3]);
        p0[1] = make_uint4(hw[4], hw[5], hw[6], hw[7]);
        p1[0] = make_uint4(lw[0], lw[1], lw[2], lw[3]);
        p1[1] = make_uint4(lw[4], lw[5], lw[6], lw[7]);
        return;
    }

    // ---- B branch: transpose + mask + split, 64x64 tile staged in smem ----
    const int kb = blockIdx.y * 64, cb = blockIdx.x * 64;
    if (kb >= (cb & ~255) + 256) return;          // k > col0+255: unread
    if (kb > cb + 63) {                           // read, but fully masked
        const uint4 z = make_uint4(0, 0, 0, 0);
        int u = tid * 2;
        int c = u >> 3, s = u & 7;
        uint4* p0 = reinterpret_cast<uint4*>(gB0 + (size_t)(cb + c) * NMAT + kb + s * 8);
        uint4* p1 = reinterpret_cast<uint4*>(gB1 + (size_t)(cb + c) * NMAT + kb + s * 8);
        p0[0] = z; p0[1] = z;
        p1[0] = z; p1[1] = z;
        return;
    }

    __shared__ float s[64][65];
    #pragma unroll
    for (int i = 0; i < 4; ++i) {
        int idx = tid + i * 256;
        int k = idx >> 4, cq = (idx & 15) * 4;
        float4 v = *reinterpret_cast<const float4*>(B + (size_t)(kb + k) * NMAT + cb + cq);
        int kg = kb + k;
        s[k][cq + 0] = (kg <= cb + cq + 0) ? v.x : 0.f;
        s[k][cq + 1] = (kg <= cb + cq + 1) ? v.y : 0.f;
        s[k][cq + 2] = (kg <= cb + cq + 2) ? v.z : 0.f;
        s[k][cq + 3] = (kg <= cb + cq + 3) ? v.w : 0.f;
    }
    __syncthreads();

    const int c = tid >> 2;
    const int ks = (tid & 3) * 16;
    float f[16];
    #pragma unroll
    for (int j = 0; j < 16; ++j) f[j] = s[ks + j][c];
    uint32_t h[8], l[8];
    #pragma unroll
    for (int j = 0; j < 8; ++j) {
        float x0 = f[2 * j], x1 = f[2 * j + 1];
        float h0 = __bfloat162float(__float2bfloat16(x0));
        float h1 = __bfloat162float(__float2bfloat16(x1));
        h[j] = pack_bf16x2(x0, x1);
        l[j] = pack_bf16x2(x0 - h0, x1 - h1);
    }
    uint4* p0 = reinterpret_cast<uint4*>(gB0 + (size_t)(cb + c) * NMAT + kb + ks);
    uint4* p1 = reinterpret_cast<uint4*>(gB1 + (size_t)(cb + c) * NMAT + kb + ks);
    p0[0] = make_uint4(h[0], h[1], h[2], h[3]);
    p0[1] = make_uint4(h[4], h[5], h[6], h[7]);
    p1[0] = make_uint4(l[0], l[1], l[2], l[3]);
    p1[1] = make_uint4(l[4], l[5], l[6], l[7]);
}

// ---------------------------------------------------------------- main GEMM
// smem: ctrl @ +0 (tmemptr @0, mbar[s] @8+8s); STAGES x 48KB buffers @ +1024.
constexpr int OFF_A0 = 0;
constexpr int OFF_A1 = 8192;
constexpr int OFF_B0 = 16384;
constexpr int OFF_B1 = 32768;
constexpr int STAGE_SZ = 49152;
constexpr int SMEM_NEED = 1024 + STAGES * STAGE_SZ + 1024;

#if defined(__CUDA_ARCH_FEAT_SM103_ALL) || !defined(__CUDA_ARCH__)
__device__ __forceinline__ void issue_chunk(uint32_t bb, int row0, int col0,
                                            int kt, int tid) {
    #pragma unroll
    for (int j = 0; j < 2; ++j) {
        int idx = tid + j * THREADS;           // A: 512 segs each
        int m = idx >> 2, seg = idx & 3;
        uint32_t off = m * 64 + seg * 16;
        off ^= (off >> 3) & 0x30;              // SW64
        const __nv_bfloat16* s0 = gA0 + (size_t)(row0 + m) * NMAT + kt + seg * 8;
        const __nv_bfloat16* s1 = gA1 + (size_t)(row0 + m) * NMAT + kt + seg * 8;
        cp_async16(bb + OFF_A0 + off, s0);
        cp_async16(bb + OFF_A1 + off, s1);
    }
    #pragma unroll
    for (int j = 0; j < 4; ++j) {
        int idx = tid + j * THREADS;           // B: 1024 segs each
        int crow = idx >> 2, seg = idx & 3;
        uint32_t off = crow * 64 + seg * 16;
        off ^= (off >> 3) & 0x30;              // SW64
        const __nv_bfloat16* s0 = gB0 + (size_t)(col0 + crow) * NMAT + kt + seg * 8;
        const __nv_bfloat16* s1 = gB1 + (size_t)(col0 + crow) * NMAT + kt + seg * 8;
        cp_async16(bb + OFF_B0 + off, s0);
        cp_async16(bb + OFF_B1 + off, s1);
    }
}
#endif

__global__ __launch_bounds__(THREADS, 1)
void trimm_tc_kernel(const float* __restrict__ A,
                     const float* __restrict__ B,
                     float* __restrict__ C) {
    const int bc2 = blockIdx.x, br = blockIdx.y, sg = blockIdx.z;
    const int row0 = br * BM, col0 = bc2 * BN;
    const int tid = threadIdx.x;

    // Fully-lower tiles: write zeros once (out is poisoned).
    if (row0 > col0 + BN - 1) {
        if (sg != 0) return;
        const float4 z = make_float4(0.f, 0.f, 0.f, 0.f);
        float4* out = reinterpret_cast<float4*>(C + (size_t)row0 * NMAT + col0);
        #pragma unroll
        for (int i = 0; i < (BM * BN / 4) / THREADS; ++i) {
            int idx = tid + i * THREADS;
            out[(size_t)(idx >> 6) * (NMAT / 4) + (idx & 63)] = z;
        }
        return;
    }

    const int nch = (col0 + BN - row0) / KC;
    const int nseg = (nch + SEG - 1) / SEG;
    if (sg >= nseg) return;
    const int c0 = sg * SEG;
    const int cnt = min(SEG, nch - c0);          // always >= 4
    const int kb0 = row0 + c0 * KC;
    float* outp = (nseg == 1) ? C : (gPart + (size_t)sg * NMAT * NMAT);

#if defined(__CUDA_ARCH__) && !defined(__CUDA_ARCH_FEAT_SM103_ALL)
    // ---------------- arch-generic fallback: SIMT fp32, same segmentation ---
    constexpr int BK = 8, TM = 8, TN = 8;
    __shared__ float As[BK][128 + 4];
    __shared__ float Bs[BK][128];

    const int ty = tid >> 4, tx = tid & 15;
    const int a_row = tid >> 1, a_k = (tid & 1) * 4;
    const int b_k = tid >> 5, b_col = (tid & 31) * 4;
    const int arow_g = row0 + a_row;
    const int kseg_end = kb0 + cnt * KC;

    for (int h = 0; h < 2; ++h) {
        const int col0h = col0 + h * 128;
        float acc[TM][TN];
        #pragma unroll
        for (int i = 0; i < TM; ++i)
            #pragma unroll
            for (int j = 0; j < TN; ++j) acc[i][j] = 0.f;
        const int cg = col0h + b_col;
        __syncthreads();
        for (int kt = kb0; kt < kseg_end; kt += BK) {
            {
                const float4 av = *reinterpret_cast<const float4*>(
                    A + (size_t)arow_g * NMAT + (kt + a_k));
                const int kg = kt + a_k;
                As[a_k + 0][a_row] = (kg + 0 >= arow_g) ? av.x : 0.f;
                As[a_k + 1][a_row] = (kg + 1 >= arow_g) ? av.y : 0.f;
                As[a_k + 2][a_row] = (kg + 2 >= arow_g) ? av.z : 0.f;
                As[a_k + 3][a_row] = (kg + 3 >= arow_g) ? av.w : 0.f;
            }
            {
                const int bkg = kt + b_k;
                float4 bv = *reinterpret_cast<const float4*>(B + (size_t)bkg * NMAT + cg);
                bv.x = (bkg <= cg + 0) ? bv.x : 0.f;
                bv.y = (bkg <= cg + 1) ? bv.y : 0.f;
                bv.z = (bkg <= cg + 2) ? bv.z : 0.f;
                bv.w = (bkg <= cg + 3) ? bv.w : 0.f;
                *reinterpret_cast<float4*>(&Bs[b_k][b_col]) = bv;
            }
            __syncthreads();
            #pragma unroll
            for (int kk = 0; kk < BK; ++kk) {
                float ar[TM], bb[TN];
                #pragma unroll
                for (int i = 0; i < TM; ++i) ar[i] = As[kk][ty * TM + i];
                #pragma unroll
                for (int j = 0; j < TN; ++j) bb[j] = Bs[kk][tx * TN + j];
                #pragma unroll
                for (int i = 0; i < TM; ++i)
                    #pragma unroll
                    for (int j = 0; j < TN; ++j)
                        acc[i][j] = fmaf(ar[i], bb[j], acc[i][j]);
            }
            __syncthreads();
        }
        #pragma unroll
        for (int i = 0; i < TM; ++i) {
            float4* crow = reinterpret_cast<float4*>(
                outp + (size_t)(row0 + ty * TM + i) * NMAT + col0h + tx * TN);
            crow[0] = make_float4(acc[i][0], acc[i][1], acc[i][2], acc[i][3]);
            crow[1] = make_float4(acc[i][4], acc[i][5], acc[i][6], acc[i][7]);
        }
    }
#else
    // ---------------- sm_103a fast path: 4-stage cp.async -> tcgen05 --------
    const int wid = tid >> 5, lid = tid & 31;

    extern __shared__ char dsm[];
    const uint32_t raw = smem_u32(dsm);
    const uint32_t sb = (raw + 1023u) & ~1023u;
    const uint32_t s_tmemptr = sb;
    const uint32_t s_mbar = sb + 8;

    if (wid == 0) { TC_ALLOC(s_tmemptr, 256); TC_RELINQ(); }
    if (tid == 0) {
        #pragma unroll
        for (int s = 0; s < STAGES; ++s) MBAR_INIT(s_mbar + 8 * s, 1);
    }
    __syncthreads();
    uint32_t tmem;
    asm volatile("ld.shared.b32 %0, [%1];" : "=r"(tmem) : "r"(s_tmemptr));

    const bool lead = (wid == 0) ? (elect_one() != 0) : false;

    // idesc kind::f16: dtype=F32, a/btype=BF16, N=256, M=128
    const uint32_t idesc = (1u << 4) | (1u << 7) | (1u << 10)
                         | ((BN / 8) << 17) | ((BM / 16) << 24);

    // prologue: fill stages 0..2 (cnt >= 4 always)
    #pragma unroll
    for (int s = 0; s < 3; ++s) {
        issue_chunk(sb + 1024 + s * STAGE_SZ, row0, col0, kb0 + s * KC, tid);
        CP_COMMIT();
    }

    for (int c = 0; c < cnt; ++c) {
        const int slot = c & 3;
        const uint32_t bb = sb + 1024 + slot * STAGE_SZ;

        const int rem = cnt - 1 - c;
        if (rem >= 2) { CP_WAIT2(); } else if (rem == 1) { CP_WAIT1(); } else { CP_WAIT0(); }
        __syncthreads();

        if (lead) {
            FENCE_ASYNC();
            const uint64_t dA0 = mk_desc64(bb + OFF_A0);
            const uint64_t dA1 = mk_desc64(bb + OFF_A1);
            const uint64_t dB0 = mk_desc64(bb + OFF_B0);
            const uint64_t dB1 = mk_desc64(bb + OFF_B1);
            #pragma unroll
            for (int s = 0; s < 2; ++s) {
                mma_f16_ss(tmem, dA0 + 2 * s, dB0 + 2 * s, idesc,
                           (c > 0 || s > 0) ? 1u : 0u);
                mma_f16_ss(tmem, dA0 + 2 * s, dB1 + 2 * s, idesc, 1u);
                mma_f16_ss(tmem, dA1 + 2 * s, dB0 + 2 * s, idesc, 1u);
            }
            TC_COMMIT(s_mbar + 8 * slot);
        }

        if (c + 3 < cnt) {
            if (c >= 1) MBAR_WAIT_PARITY(s_mbar + 8 * ((c - 1) & 3), ((c - 1) >> 2) & 1);
            issue_chunk(sb + 1024 + ((c + 3) & 3) * STAGE_SZ, row0, col0,
                        kb0 + (c + 3) * KC, tid);
            CP_COMMIT();
        }
    }

    {
        const int L = cnt - 1;
        MBAR_WAIT_PARITY(s_mbar + 8 * (L & 3), (L >> 2) & 1);
    }
    TC_FENCE_AFTER();

    // epilogue: 8 warps; warp w covers rows (w&3)*32+lid, col half=(w>>2)*128
    {
        const int wsub = wid & 3, half = wid >> 2;
        const int r = row0 + wsub * 32 + lid;
        #pragma unroll
        for (int batch = 0; batch < 4; ++batch) {
            uint32_t rg[32];
            LDTM_X32(rg, tmem + half * 128 + batch * 32);
            TC_WAIT_LD();
            float4* dst = reinterpret_cast<float4*>(
                outp + (size_t)r * NMAT + col0 + half * 128 + batch * 32);
            #pragma unroll
            for (int q = 0; q < 8; ++q)
                dst[q] = make_float4(__uint_as_float(rg[4 * q + 0]),
                                     __uint_as_float(rg[4 * q + 1]),
                                     __uint_as_float(rg[4 * q + 2]),
                                     __uint_as_float(rg[4 * q + 3]));
        }
        TC_FENCE_BEFORE();
    }
    __syncthreads();
    if (wid == 0) { TC_DEALLOC(tmem, 256); }
#endif
}

// ---------------------------------------------------------------- reduce
// For tiles with nseg >= 2: C = sum of partial slabs over the tile region.
__global__ __launch_bounds__(256)
void reduce_kernel(float* __restrict__ C) {
    const int bc2 = blockIdx.x, br = blockIdx.y;
    const int row0 = br * BM, col0 = bc2 * BN;
    if (row0 > col0 + BN - 1) return;
    const int nch = (col0 + BN - row0) / KC;
    const int nseg = (nch + SEG - 1) / SEG;
    if (nseg == 1) return;
    const int tid = threadIdx.x;
    const size_t slab = (size_t)NMAT * NMAT / 4;   // in float4 units
    const float4* P = reinterpret_cast<const float4*>(gPart);
    float4* Co = reinterpret_cast<float4*>(C);

    #pragma unroll
    for (int i = 0; i < 32; ++i) {
        int idx = tid + i * 256;                   // 0..8191 float4
        int r = idx >> 6, cq = idx & 63;
        size_t e = ((size_t)(row0 + r) * NMAT + col0) / 4 + cq;
        float4 a = P[e];
        for (int s = 1; s < nseg; ++s) {
            float4 b = P[s * slab + e];
            a.x += b.x; a.y += b.y; a.z += b.z; a.w += b.w;
        }
        Co[e] = a;
    }
}

// ---------------------------------------------------------------- launch
extern "C" void kernel_launch(void* const* d_in, const int* in_sizes, int n_in,
                              void* d_out, int out_size) {
    const float* A = (const float*)d_in[0];
    const float* B = (const float*)d_in[1];
    float* C = (float*)d_out;

    cudaFuncSetAttribute(trimm_tc_kernel,
                         cudaFuncAttributeMaxDynamicSharedMemorySize, SMEM_NEED);

    split_ab_kernel<<<dim3(NMAT / 64, NMAT / 64, 2), 256>>>(A, B);
    trimm_tc_kernel<<<dim3(NMAT / BN, NMAT / BM, MAXSEG), THREADS, SMEM_NEED>>>(A, B, C);
    reduce_kernel<<<dim3(NMAT / BN, NMAT / BM), 256>>>(C);
}

// round 8
// speedup vs baseline: 1.2567x; 1.2567x over previous
#include <cuda_runtime.h>
#include <cuda_bf16.h>
#include <cstdint>

// C = triu(triu(A) @ triu(B)), N = 4096, fp32.
// sm_103a path: A,B pre-split into masked bf16 hi/lo (B transposed K-major);
// main kernel: 4-stage cp.async -> tcgen05 pipeline, KC=32 (SW64 64B rows),
// 3 bf16 MMAs per K16 (h*h + h*l + l*h), fp32 accum in TMEM, 128x256 tiles.
// Selective split-K: only tiles with >=64 k-chunks split 2-way (partials in
// fp32 slabs, summed by a small reduce kernel over those tiles only).
// Fallback (arch-generic PTX): SIMT fp32 kernel with the same segmentation.

constexpr int NMAT = 4096;
constexpr int BM = 128;
constexpr int BN = 256;
constexpr int KC = 32;         // k-chunk (32 bf16 = 64B rows, SW64 native)
constexpr int THREADS = 256;
constexpr int STAGES = 4;
constexpr int SPLIT_NCH = 64;  // tiles with nch >= this split 2-way
constexpr int MAXSEG = 2;

// Scratch: masked splits. gA0/gA1: A [r][k]. gB0/gB1: B^T [c][k]. All K-major.
__device__ __align__(1024) __nv_bfloat16 gA0[(size_t)NMAT * NMAT];
__device__ __align__(1024) __nv_bfloat16 gA1[(size_t)NMAT * NMAT];
__device__ __align__(1024) __nv_bfloat16 gB0[(size_t)NMAT * NMAT];
__device__ __align__(1024) __nv_bfloat16 gB1[(size_t)NMAT * NMAT];
// Split-K partial slabs (fp32), one full matrix per segment index.
__device__ __align__(1024) float gPart[(size_t)MAXSEG * NMAT * NMAT];

// ---------------------------------------------------------------- helpers
__device__ __forceinline__ uint32_t smem_u32(const void* p) {
    uint32_t a;
    asm("{ .reg .u64 t; cvta.to.shared.u64 t, %1; cvt.u32.u64 %0, t; }"
        : "=r"(a) : "l"(p));
    return a;
}

#if defined(__CUDA_ARCH_FEAT_SM103_ALL) || !defined(__CUDA_ARCH__)
__device__ __forceinline__ uint32_t elect_one() {
    uint32_t p;
    asm volatile("{ .reg .pred p; elect.sync _|p, 0xFFFFFFFF; selp.b32 %0,1,0,p; }"
                 : "=r"(p));
    return p;
}
__device__ __forceinline__ void mma_f16_ss(uint32_t d, uint64_t ad, uint64_t bd,
                                           uint32_t idesc, uint32_t en) {
    asm volatile(
        "{\n\t.reg .pred p;\n\tsetp.ne.u32 p, %5, 0;\n\t"
        "tcgen05.mma.cta_group::1.kind::f16 [%0], %1, %2, %3, {%4,%4,%4,%4}, p;\n\t}"
        :: "r"(d), "l"(ad), "l"(bd), "r"(idesc), "r"(0u), "r"(en) : "memory");
}
__device__ __forceinline__ void cp_async16(uint32_t dst, const void* src) {
    asm volatile("cp.async.cg.shared.global [%0], [%1], 16;"
                 :: "r"(dst), "l"(src) : "memory");
}
#define CP_COMMIT()      asm volatile("cp.async.commit_group;" ::: "memory")
#define CP_WAIT0()       asm volatile("cp.async.wait_group 0;" ::: "memory")
#define CP_WAIT1()       asm volatile("cp.async.wait_group 1;" ::: "memory")
#define CP_WAIT2()       asm volatile("cp.async.wait_group 2;" ::: "memory")
#define TC_ALLOC(sl, n)  asm volatile("tcgen05.alloc.cta_group::1.sync.aligned.shared::cta.b32 [%0], %1;" :: "r"(sl), "r"((uint32_t)(n)) : "memory")
#define TC_RELINQ()      asm volatile("tcgen05.relinquish_alloc_permit.cta_group::1.sync.aligned;")
#define TC_DEALLOC(t, n) asm volatile("tcgen05.dealloc.cta_group::1.sync.aligned.b32 %0, %1;" :: "r"(t), "r"((uint32_t)(n)))
#define TC_COMMIT(mb)    asm volatile("tcgen05.commit.cta_group::1.mbarrier::arrive::one.shared::cluster.b64 [%0];" :: "r"(mb) : "memory")
#define TC_FENCE_AFTER() asm volatile("tcgen05.fence::after_thread_sync;" ::: "memory")
#define TC_FENCE_BEFORE() asm volatile("tcgen05.fence::before_thread_sync;" ::: "memory")
#define TC_WAIT_LD()     asm volatile("tcgen05.wait::ld.sync.aligned;" ::: "memory")
#define FENCE_ASYNC()    asm volatile("fence.proxy.async.shared::cta;" ::: "memory")
#define MBAR_INIT(mb, c) asm volatile("mbarrier.init.shared.b64 [%0], %1;" :: "r"(mb), "r"((uint32_t)(c)) : "memory")

#define MBAR_WAIT_PARITY(mb, ph) do {                                           \
    uint32_t _m = (mb), _p = (ph), _d;                                          \
    asm volatile("{\n\t.reg .pred p;\n\t"                                       \
        "mbarrier.try_wait.parity.acquire.cta.shared::cta.b64 p, [%1], %2;\n\t" \
        "selp.b32 %0, 1, 0, p;\n\t}" : "=r"(_d) : "r"(_m), "r"(_p) : "memory"); \
    if (!_d) {                                                                  \
        asm volatile("{\n\t.reg .pred P1;\n\t"                                  \
        "WL_%=:\n\t"                                                            \
        "mbarrier.try_wait.parity.acquire.cta.shared::cta.b64 P1, [%0], %1, 0x989680;\n\t" \
        "@P1 bra.uni WD_%=;\n\t"                                                \
        "bra.uni WL_%=;\n\t"                                                    \
        "WD_%=:\n\t}" :: "r"(_m), "r"(_p) : "memory");                          \
    }                                                                           \
} while (0)

#define LDTM_X32(r, a)                                                          \
    asm volatile("tcgen05.ld.sync.aligned.32x32b.x32.b32 "                      \
        "{%0, %1, %2, %3, %4, %5, %6, %7, %8, %9, %10, %11, %12, %13, %14, %15,"\
        " %16, %17, %18, %19, %20, %21, %22, %23, %24, %25, %26, %27, %28, %29, %30, %31}, [%32];" \
        : "=r"((r)[0]), "=r"((r)[1]), "=r"((r)[2]), "=r"((r)[3]),               \
          "=r"((r)[4]), "=r"((r)[5]), "=r"((r)[6]), "=r"((r)[7]),               \
          "=r"((r)[8]), "=r"((r)[9]), "=r"((r)[10]), "=r"((r)[11]),             \
          "=r"((r)[12]), "=r"((r)[13]), "=r"((r)[14]), "=r"((r)[15]),           \
          "=r"((r)[16]), "=r"((r)[17]), "=r"((r)[18]), "=r"((r)[19]),           \
          "=r"((r)[20]), "=r"((r)[21]), "=r"((r)[22]), "=r"((r)[23]),           \
          "=r"((r)[24]), "=r"((r)[25]), "=r"((r)[26]), "=r"((r)[27]),           \
          "=r"((r)[28]), "=r"((r)[29]), "=r"((r)[30]), "=r"((r)[31])            \
        : "r"(a))
#endif  // tcgen05 helpers

// SW64 smem descriptor (K-major, 64B rows): layout=SW64(4), ver=1, SBO=32, LBO=1
constexpr uint64_t DESC_BASE_SW64 =
    (uint64_t(4) << 61) | (uint64_t(1) << 46) | (uint64_t(32) << 32) | (uint64_t(1) << 16);
__device__ __forceinline__ uint64_t mk_desc64(uint32_t a) {
    return DESC_BASE_SW64 | ((uint64_t)(a >> 4) & 0x3FFF);
}

__device__ __forceinline__ uint32_t pack_bf16x2(float a, float b) {
    __nv_bfloat162 h = __halves2bfloat162(__float2bfloat16(a), __float2bfloat16(b));
    return *reinterpret_cast<uint32_t*>(&h);
}

// ---------------------------------------------------------------- pre-pass
// z=0: gA0/gA1[r][k] = hi/lo bf16 of (k>=r ? A[r][k] : 0)   (row-major copy)
// z=1: gB0/gB1[c][k] = hi/lo bf16 of (k<=c ? B[k][c] : 0)   (transpose)
// Regions never read by the main kernel are skipped entirely.
__global__ __launch_bounds__(256)
void split_ab_kernel(const float* __restrict__ A, const float* __restrict__ B) {
    const int tid = threadIdx.x;

    if (blockIdx.z == 0) {
        const int rb = blockIdx.y * 64, kb = blockIdx.x * 64;
        if (kb < (rb & ~127)) return;            // k < row0 of main tile: unread
        const int r = rb + (tid >> 2);
        const int k0 = kb + (tid & 3) * 16;
        uint32_t hw[8], lw[8];
        if (kb + 63 < rb) {                       // read, but fully masked
            #pragma unroll
            for (int i = 0; i < 8; ++i) { hw[i] = 0u; lw[i] = 0u; }
        } else {
            #pragma unroll
            for (int q = 0; q < 4; ++q) {
                float4 v = *reinterpret_cast<const float4*>(
                    A + (size_t)r * NMAT + k0 + q * 4);
                const int kg = k0 + q * 4;
                float x0 = (kg + 0 >= r) ? v.x : 0.f;
                float x1 = (kg + 1 >= r) ? v.y : 0.f;
                float x2 = (kg + 2 >= r) ? v.z : 0.f;
                float x3 = (kg + 3 >= r) ? v.w : 0.f;
                float h0 = __bfloat162float(__float2bfloat16(x0));
                float h1 = __bfloat162float(__float2bfloat16(x1));
                float h2 = __bfloat162float(__float2bfloat16(x2));
                float h3 = __bfloat162float(__float2bfloat16(x3));
                hw[2 * q + 0] = pack_bf16x2(x0, x1);
                hw[2 * q + 1] = pack_bf16x2(x2, x3);
                lw[2 * q + 0] = pack_bf16x2(x0 - h0, x1 - h1);
                lw[2 * q + 1] = pack_bf16x2(x2 - h2, x3 - h3);
            }
        }
        uint4* p0 = reinterpret_cast<uint4*>(gA0 + (size_t)r * NMAT + k0);
        uint4* p1 = reinterpret_cast<uint4*>(gA1 + (size_t)r * NMAT + k0);
        p0[0] = make_uint4(hw[0], hw[1], hw[2], hw[3]);
        p0[1] = make_uint4(hw[4], hw[5], hw[6], hw[7]);
        p1[0] = make_uint4(lw[0], lw[1], lw[2], lw[3]);
        p1[1] = make_uint4(lw[4], lw[5], lw[6], lw[7]);
        return;
    }

    // ---- B branch: transpose + mask + split, 64x64 tile staged in smem ----
    const int kb = blockIdx.y * 64, cb = blockIdx.x * 64;
    if (kb >= (cb & ~255) + 256) return;          // k > col0+255: unread
    if (kb > cb + 63) {                           // read, but fully masked
        const uint4 z = make_uint4(0, 0, 0, 0);
        int u = tid * 2;
        int c = u >> 3, s = u & 7;
        uint4* p0 = reinterpret_cast<uint4*>(gB0 + (size_t)(cb + c) * NMAT + kb + s * 8);
        uint4* p1 = reinterpret_cast<uint4*>(gB1 + (size_t)(cb + c) * NMAT + kb + s * 8);
        p0[0] = z; p0[1] = z;
        p1[0] = z; p1[1] = z;
        return;
    }

    __shared__ float s[64][65];
    #pragma unroll
    for (int i = 0; i < 4; ++i) {
        int idx = tid + i * 256;
        int k = idx >> 4, cq = (idx & 15) * 4;
        float4 v = *reinterpret_cast<const float4*>(B + (size_t)(kb + k) * NMAT + cb + cq);
        int kg = kb + k;
        s[k][cq + 0] = (kg <= cb + cq + 0) ? v.x : 0.f;
        s[k][cq + 1] = (kg <= cb + cq + 1) ? v.y : 0.f;
        s[k][cq + 2] = (kg <= cb + cq + 2) ? v.z : 0.f;
        s[k][cq + 3] = (kg <= cb + cq + 3) ? v.w : 0.f;
    }
    __syncthreads();

    const int c = tid >> 2;
    const int ks = (tid & 3) * 16;
    float f[16];
    #pragma unroll
    for (int j = 0; j < 16; ++j) f[j] = s[ks + j][c];
    uint32_t h[8], l[8];
    #pragma unroll
    for (int j = 0; j < 8; ++j) {
        float x0 = f[2 * j], x1 = f[2 * j + 1];
        float h0 = __bfloat162float(__float2bfloat16(x0));
        float h1 = __bfloat162float(__float2bfloat16(x1));
        h[j] = pack_bf16x2(x0, x1);
        l[j] = pack_bf16x2(x0 - h0, x1 - h1);
    }
    uint4* p0 = reinterpret_cast<uint4*>(gB0 + (size_t)(cb + c) * NMAT + kb + ks);
    uint4* p1 = reinterpret_cast<uint4*>(gB1 + (size_t)(cb + c) * NMAT + kb + ks);
    p0[0] = make_uint4(h[0], h[1], h[2], h[3]);
    p0[1] = make_uint4(h[4], h[5], h[6], h[7]);
    p1[0] = make_uint4(l[0], l[1], l[2], l[3]);
    p1[1] = make_uint4(l[4], l[5], l[6], l[7]);
}

// ---------------------------------------------------------------- main GEMM
// smem: ctrl @ +0 (tmemptr @0, mbar[s] @8+8s); STAGES x 48KB buffers @ +1024.
constexpr int OFF_A0 = 0;
constexpr int OFF_A1 = 8192;
constexpr int OFF_B0 = 16384;
constexpr int OFF_B1 = 32768;
constexpr int STAGE_SZ = 49152;
constexpr int SMEM_NEED = 1024 + STAGES * STAGE_SZ + 1024;

#if defined(__CUDA_ARCH_FEAT_SM103_ALL) || !defined(__CUDA_ARCH__)
__device__ __forceinline__ void issue_chunk(uint32_t bb, int row0, int col0,
                                            int kt, int tid) {
    #pragma unroll
    for (int j = 0; j < 2; ++j) {
        int idx = tid + j * THREADS;           // A: 512 segs each
        int m = idx >> 2, seg = idx & 3;
        uint32_t off = m * 64 + seg * 16;
        off ^= (off >> 3) & 0x30;              // SW64
        const __nv_bfloat16* s0 = gA0 + (size_t)(row0 + m) * NMAT + kt + seg * 8;
        const __nv_bfloat16* s1 = gA1 + (size_t)(row0 + m) * NMAT + kt + seg * 8;
        cp_async16(bb + OFF_A0 + off, s0);
        cp_async16(bb + OFF_A1 + off, s1);
    }
    #pragma unroll
    for (int j = 0; j < 4; ++j) {
        int idx = tid + j * THREADS;           // B: 1024 segs each
        int crow = idx >> 2, seg = idx & 3;
        uint32_t off = crow * 64 + seg * 16;
        off ^= (off >> 3) & 0x30;              // SW64
        const __nv_bfloat16* s0 = gB0 + (size_t)(col0 + crow) * NMAT + kt + seg * 8;
        const __nv_bfloat16* s1 = gB1 + (size_t)(col0 + crow) * NMAT + kt + seg * 8;
        cp_async16(bb + OFF_B0 + off, s0);
        cp_async16(bb + OFF_B1 + off, s1);
    }
}
#endif

__global__ __launch_bounds__(THREADS, 1)
void trimm_tc_kernel(const float* __restrict__ A,
                     const float* __restrict__ B,
                     float* __restrict__ C) {
    const int bc2 = blockIdx.x, br = blockIdx.y, sg = blockIdx.z;
    const int row0 = br * BM, col0 = bc2 * BN;
    const int tid = threadIdx.x;

    // Fully-lower tiles: write zeros once (out is poisoned).
    if (row0 > col0 + BN - 1) {
        if (sg != 0) return;
        const float4 z = make_float4(0.f, 0.f, 0.f, 0.f);
        float4* out = reinterpret_cast<float4*>(C + (size_t)row0 * NMAT + col0);
        #pragma unroll
        for (int i = 0; i < (BM * BN / 4) / THREADS; ++i) {
            int idx = tid + i * THREADS;
            out[(size_t)(idx >> 6) * (NMAT / 4) + (idx & 63)] = z;
        }
        return;
    }

    const int nch = (col0 + BN - row0) / KC;     // divisible by 4, >= 4
    const int nseg = (nch >= SPLIT_NCH) ? 2 : 1;
    if (sg >= nseg) return;
    const int cnt = (nseg == 1) ? nch : (nch / 2);   // >= 4 always
    const int kb0 = row0 + sg * cnt * KC;
    float* outp = (nseg == 1) ? C : (gPart + (size_t)sg * NMAT * NMAT);

#if defined(__CUDA_ARCH__) && !defined(__CUDA_ARCH_FEAT_SM103_ALL)
    // ---------------- arch-generic fallback: SIMT fp32, same segmentation ---
    constexpr int BK = 8, TM = 8, TN = 8;
    __shared__ float As[BK][128 + 4];
    __shared__ float Bs[BK][128];

    const int ty = tid >> 4, tx = tid & 15;
    const int a_row = tid >> 1, a_k = (tid & 1) * 4;
    const int b_k = tid >> 5, b_col = (tid & 31) * 4;
    const int arow_g = row0 + a_row;
    const int kseg_end = kb0 + cnt * KC;

    for (int h = 0; h < 2; ++h) {
        const int col0h = col0 + h * 128;
        float acc[TM][TN];
        #pragma unroll
        for (int i = 0; i < TM; ++i)
            #pragma unroll
            for (int j = 0; j < TN; ++j) acc[i][j] = 0.f;
        const int cg = col0h + b_col;
        __syncthreads();
        for (int kt = kb0; kt < kseg_end; kt += BK) {
            {
                const float4 av = *reinterpret_cast<const float4*>(
                    A + (size_t)arow_g * NMAT + (kt + a_k));
                const int kg = kt + a_k;
                As[a_k + 0][a_row] = (kg + 0 >= arow_g) ? av.x : 0.f;
                As[a_k + 1][a_row] = (kg + 1 >= arow_g) ? av.y : 0.f;
                As[a_k + 2][a_row] = (kg + 2 >= arow_g) ? av.z : 0.f;
                As[a_k + 3][a_row] = (kg + 3 >= arow_g) ? av.w : 0.f;
            }
            {
                const int bkg = kt + b_k;
                float4 bv = *reinterpret_cast<const float4*>(B + (size_t)bkg * NMAT + cg);
                bv.x = (bkg <= cg + 0) ? bv.x : 0.f;
                bv.y = (bkg <= cg + 1) ? bv.y : 0.f;
                bv.z = (bkg <= cg + 2) ? bv.z : 0.f;
                bv.w = (bkg <= cg + 3) ? bv.w : 0.f;
                *reinterpret_cast<float4*>(&Bs[b_k][b_col]) = bv;
            }
            __syncthreads();
            #pragma unroll
            for (int kk = 0; kk < BK; ++kk) {
                float ar[TM], bb[TN];
                #pragma unroll
                for (int i = 0; i < TM; ++i) ar[i] = As[kk][ty * TM + i];
                #pragma unroll
                for (int j = 0; j < TN; ++j) bb[j] = Bs[kk][tx * TN + j];
                #pragma unroll
                for (int i = 0; i < TM; ++i)
                    #pragma unroll
                    for (int j = 0; j < TN; ++j)
                        acc[i][j] = fmaf(ar[i], bb[j], acc[i][j]);
            }
            __syncthreads();
        }
        #pragma unroll
        for (int i = 0; i < TM; ++i) {
            float4* crow = reinterpret_cast<float4*>(
                outp + (size_t)(row0 + ty * TM + i) * NMAT + col0h + tx * TN);
            crow[0] = make_float4(acc[i][0], acc[i][1], acc[i][2], acc[i][3]);
            crow[1] = make_float4(acc[i][4], acc[i][5], acc[i][6], acc[i][7]);
        }
    }
#else
    // ---------------- sm_103a fast path: 4-stage cp.async -> tcgen05 --------
    const int wid = tid >> 5, lid = tid & 31;

    extern __shared__ char dsm[];
    const uint32_t raw = smem_u32(dsm);
    const uint32_t sb = (raw + 1023u) & ~1023u;
    const uint32_t s_tmemptr = sb;
    const uint32_t s_mbar = sb + 8;

    if (wid == 0) { TC_ALLOC(s_tmemptr, 256); TC_RELINQ(); }
    if (tid == 0) {
        #pragma unroll
        for (int s = 0; s < STAGES; ++s) MBAR_INIT(s_mbar + 8 * s, 1);
    }
    __syncthreads();
    uint32_t tmem;
    asm volatile("ld.shared.b32 %0, [%1];" : "=r"(tmem) : "r"(s_tmemptr));

    const bool lead = (wid == 0) ? (elect_one() != 0) : false;

    // idesc kind::f16: dtype=F32, a/btype=BF16, N=256, M=128
    const uint32_t idesc = (1u << 4) | (1u << 7) | (1u << 10)
                         | ((BN / 8) << 17) | ((BM / 16) << 24);

    // prologue: fill stages 0..2 (cnt >= 4 always)
    #pragma unroll
    for (int s = 0; s < 3; ++s) {
        issue_chunk(sb + 1024 + s * STAGE_SZ, row0, col0, kb0 + s * KC, tid);
        CP_COMMIT();
    }

    for (int c = 0; c < cnt; ++c) {
        const int slot = c & 3;
        const uint32_t bb = sb + 1024 + slot * STAGE_SZ;

        const int rem = cnt - 1 - c;
        if (rem >= 2) { CP_WAIT2(); } else if (rem == 1) { CP_WAIT1(); } else { CP_WAIT0(); }
        __syncthreads();

        if (lead) {
            FENCE_ASYNC();
            const uint64_t dA0 = mk_desc64(bb + OFF_A0);
            const uint64_t dA1 = mk_desc64(bb + OFF_A1);
            const uint64_t dB0 = mk_desc64(bb + OFF_B0);
            const uint64_t dB1 = mk_desc64(bb + OFF_B1);
            #pragma unroll
            for (int s = 0; s < 2; ++s) {
                mma_f16_ss(tmem, dA0 + 2 * s, dB0 + 2 * s, idesc,
                           (c > 0 || s > 0) ? 1u : 0u);
                mma_f16_ss(tmem, dA0 + 2 * s, dB1 + 2 * s, idesc, 1u);
                mma_f16_ss(tmem, dA1 + 2 * s, dB0 + 2 * s, idesc, 1u);
            }
            TC_COMMIT(s_mbar + 8 * slot);
        }

        if (c + 3 < cnt) {
            if (c >= 1) MBAR_WAIT_PARITY(s_mbar + 8 * ((c - 1) & 3), ((c - 1) >> 2) & 1);
            issue_chunk(sb + 1024 + ((c + 3) & 3) * STAGE_SZ, row0, col0,
                        kb0 + (c + 3) * KC, tid);
            CP_COMMIT();
        }
    }

    {
        const int L = cnt - 1;
        MBAR_WAIT_PARITY(s_mbar + 8 * (L & 3), (L >> 2) & 1);
    }
    TC_FENCE_AFTER();

    // epilogue: 8 warps; warp w covers rows (w&3)*32+lid, col half=(w>>2)*128
    {
        const int wsub = wid & 3, half = wid >> 2;
        const int r = row0 + wsub * 32 + lid;
        #pragma unroll
        for (int batch = 0; batch < 4; ++batch) {
            uint32_t rg[32];
            LDTM_X32(rg, tmem + half * 128 + batch * 32);
            TC_WAIT_LD();
            float4* dst = reinterpret_cast<float4*>(
                outp + (size_t)r * NMAT + col0 + half * 128 + batch * 32);
            #pragma unroll
            for (int q = 0; q < 8; ++q)
                dst[q] = make_float4(__uint_as_float(rg[4 * q + 0]),
                                     __uint_as_float(rg[4 * q + 1]),
                                     __uint_as_float(rg[4 * q + 2]),
                                     __uint_as_float(rg[4 * q + 3]));
        }
        TC_FENCE_BEFORE();
    }
    __syncthreads();
    if (wid == 0) { TC_DEALLOC(tmem, 256); }
#endif
}

// ---------------------------------------------------------------- reduce
// Only for split tiles (nch >= SPLIT_NCH): C = P0 + P1 over the tile region.
__global__ __launch_bounds__(256)
void reduce_kernel(float* __restrict__ C) {
    const int bc2 = blockIdx.x, br = blockIdx.y;
    const int row0 = br * BM, col0 = bc2 * BN;
    if (row0 > col0 + BN - 1) return;
    const int nch = (col0 + BN - row0) / KC;
    if (nch < SPLIT_NCH) return;
    const int tid = threadIdx.x;
    const size_t slab = (size_t)NMAT * NMAT / 4;   // in float4 units
    const float4* P = reinterpret_cast<const float4*>(gPart);
    float4* Co = reinterpret_cast<float4*>(C);

    #pragma unroll
    for (int i = 0; i < 32; ++i) {
        int idx = tid + i * 256;                   // 0..8191 float4
        int r = idx >> 6, cq = idx & 63;
        size_t e = ((size_t)(row0 + r) * NMAT + col0) / 4 + cq;
        float4 a = P[e];
        float4 b = P[slab + e];
        a.x += b.x; a.y += b.y; a.z += b.z; a.w += b.w;
        Co[e] = a;
    }
}

// ---------------------------------------------------------------- launch
extern "C" void kernel_launch(void* const* d_in, const int* in_sizes, int n_in,
                              void* d_out, int out_size) {
    const float* A = (const float*)d_in[0];
    const float* B = (const float*)d_in[1];
    float* C = (float*)d_out;

    cudaFuncSetAttribute(trimm_tc_kernel,
                         cudaFuncAttributeMaxDynamicSharedMemorySize, SMEM_NEED);

    split_ab_kernel<<<dim3(NMAT / 64, NMAT / 64, 2), 256>>>(A, B);
    trimm_tc_kernel<<<dim3(NMAT / BN, NMAT / BM, MAXSEG), THREADS, SMEM_NEED>>>(A, B, C);
    reduce_kernel<<<dim3(NMAT / BN, NMAT / BM), 256>>>(C);
}

// round 9
// speedup vs baseline: 1.4981x; 1.1921x over previous
#include <cuda_runtime.h>
#include <cuda_bf16.h>
#include <cstdint>

// C = triu(triu(A) @ triu(B)), N = 4096, fp32.
// sm_103a path: A,B pre-split into masked bf16 hi/lo (B transposed K-major);
// main kernel: 4-stage cp.async -> tcgen05 pipeline, KC=32 (SW64 64B rows),
// 3 bf16 MMAs per K16 (h*h + h*l + l*h), fp32 accum in TMEM, 128x256 tiles.
// 1D grid with longest-k-first tile schedule (corner tiles start at t=0).
// Fallback (arch-generic PTX): SIMT fp32 kernel with the same mapping.

constexpr int NMAT = 4096;
constexpr int BM = 128;
constexpr int BN = 256;
constexpr int KC = 32;         // k-chunk (32 bf16 = 64B rows, SW64 native)
constexpr int THREADS = 256;
constexpr int STAGES = 4;
constexpr int NTILES = 512;    // 32 x 16
constexpr int NCOMPUTE = 272;  // tiles with row0 <= col0+BN-1

// Scratch: masked splits. gA0/gA1: A [r][k]. gB0/gB1: B^T [c][k]. All K-major.
__device__ __align__(1024) __nv_bfloat16 gA0[(size_t)NMAT * NMAT];
__device__ __align__(1024) __nv_bfloat16 gA1[(size_t)NMAT * NMAT];
__device__ __align__(1024) __nv_bfloat16 gB0[(size_t)NMAT * NMAT];
__device__ __align__(1024) __nv_bfloat16 gB1[(size_t)NMAT * NMAT];

// ---------------------------------------------------------------- helpers
__device__ __forceinline__ uint32_t smem_u32(const void* p) {
    uint32_t a;
    asm("{ .reg .u64 t; cvta.to.shared.u64 t, %1; cvt.u32.u64 %0, t; }"
        : "=r"(a) : "l"(p));
    return a;
}

#if defined(__CUDA_ARCH_FEAT_SM103_ALL) || !defined(__CUDA_ARCH__)
__device__ __forceinline__ uint32_t elect_one() {
    uint32_t p;
    asm volatile("{ .reg .pred p; elect.sync _|p, 0xFFFFFFFF; selp.b32 %0,1,0,p; }"
                 : "=r"(p));
    return p;
}
__device__ __forceinline__ void mma_f16_ss(uint32_t d, uint64_t ad, uint64_t bd,
                                           uint32_t idesc, uint32_t en) {
    asm volatile(
        "{\n\t.reg .pred p;\n\tsetp.ne.u32 p, %5, 0;\n\t"
        "tcgen05.mma.cta_group::1.kind::f16 [%0], %1, %2, %3, {%4,%4,%4,%4}, p;\n\t}"
        :: "r"(d), "l"(ad), "l"(bd), "r"(idesc), "r"(0u), "r"(en) : "memory");
}
__device__ __forceinline__ void cp_async16(uint32_t dst, const void* src) {
    asm volatile("cp.async.cg.shared.global [%0], [%1], 16;"
                 :: "r"(dst), "l"(src) : "memory");
}
#define CP_COMMIT()      asm volatile("cp.async.commit_group;" ::: "memory")
#define CP_WAIT0()       asm volatile("cp.async.wait_group 0;" ::: "memory")
#define CP_WAIT1()       asm volatile("cp.async.wait_group 1;" ::: "memory")
#define CP_WAIT2()       asm volatile("cp.async.wait_group 2;" ::: "memory")
#define TC_ALLOC(sl, n)  asm volatile("tcgen05.alloc.cta_group::1.sync.aligned.shared::cta.b32 [%0], %1;" :: "r"(sl), "r"((uint32_t)(n)) : "memory")
#define TC_RELINQ()      asm volatile("tcgen05.relinquish_alloc_permit.cta_group::1.sync.aligned;")
#define TC_DEALLOC(t, n) asm volatile("tcgen05.dealloc.cta_group::1.sync.aligned.b32 %0, %1;" :: "r"(t), "r"((uint32_t)(n)))
#define TC_COMMIT(mb)    asm volatile("tcgen05.commit.cta_group::1.mbarrier::arrive::one.shared::cluster.b64 [%0];" :: "r"(mb) : "memory")
#define TC_FENCE_AFTER() asm volatile("tcgen05.fence::after_thread_sync;" ::: "memory")
#define TC_FENCE_BEFORE() asm volatile("tcgen05.fence::before_thread_sync;" ::: "memory")
#define TC_WAIT_LD()     asm volatile("tcgen05.wait::ld.sync.aligned;" ::: "memory")
#define FENCE_ASYNC()    asm volatile("fence.proxy.async.shared::cta;" ::: "memory")
#define MBAR_INIT(mb, c) asm volatile("mbarrier.init.shared.b64 [%0], %1;" :: "r"(mb), "r"((uint32_t)(c)) : "memory")

#define MBAR_WAIT_PARITY(mb, ph) do {                                           \
    uint32_t _m = (mb), _p = (ph), _d;                                          \
    asm volatile("{\n\t.reg .pred p;\n\t"                                       \
        "mbarrier.try_wait.parity.acquire.cta.shared::cta.b64 p, [%1], %2;\n\t" \
        "selp.b32 %0, 1, 0, p;\n\t}" : "=r"(_d) : "r"(_m), "r"(_p) : "memory"); \
    if (!_d) {                                                                  \
        asm volatile("{\n\t.reg .pred P1;\n\t"                                  \
        "WL_%=:\n\t"                                                            \
        "mbarrier.try_wait.parity.acquire.cta.shared::cta.b64 P1, [%0], %1, 0x989680;\n\t" \
        "@P1 bra.uni WD_%=;\n\t"                                                \
        "bra.uni WL_%=;\n\t"                                                    \
        "WD_%=:\n\t}" :: "r"(_m), "r"(_p) : "memory");                          \
    }                                                                           \
} while (0)

#define LDTM_X32(r, a)                                                          \
    asm volatile("tcgen05.ld.sync.aligned.32x32b.x32.b32 "                      \
        "{%0, %1, %2, %3, %4, %5, %6, %7, %8, %9, %10, %11, %12, %13, %14, %15,"\
        " %16, %17, %18, %19, %20, %21, %22, %23, %24, %25, %26, %27, %28, %29, %30, %31}, [%32];" \
        : "=r"((r)[0]), "=r"((r)[1]), "=r"((r)[2]), "=r"((r)[3]),               \
          "=r"((r)[4]), "=r"((r)[5]), "=r"((r)[6]), "=r"((r)[7]),               \
          "=r"((r)[8]), "=r"((r)[9]), "=r"((r)[10]), "=r"((r)[11]),             \
          "=r"((r)[12]), "=r"((r)[13]), "=r"((r)[14]), "=r"((r)[15]),           \
          "=r"((r)[16]), "=r"((r)[17]), "=r"((r)[18]), "=r"((r)[19]),           \
          "=r"((r)[20]), "=r"((r)[21]), "=r"((r)[22]), "=r"((r)[23]),           \
          "=r"((r)[24]), "=r"((r)[25]), "=r"((r)[26]), "=r"((r)[27]),           \
          "=r"((r)[28]), "=r"((r)[29]), "=r"((r)[30]), "=r"((r)[31])            \
        : "r"(a))
#endif  // tcgen05 helpers

// SW64 smem descriptor (K-major, 64B rows): layout=SW64(4), ver=1, SBO=32, LBO=1
constexpr uint64_t DESC_BASE_SW64 =
    (uint64_t(4) << 61) | (uint64_t(1) << 46) | (uint64_t(32) << 32) | (uint64_t(1) << 16);
__device__ __forceinline__ uint64_t mk_desc64(uint32_t a) {
    return DESC_BASE_SW64 | ((uint64_t)(a >> 4) & 0x3FFF);
}

__device__ __forceinline__ uint32_t pack_bf16x2(float a, float b) {
    __nv_bfloat162 h = __halves2bfloat162(__float2bfloat16(a), __float2bfloat16(b));
    return *reinterpret_cast<uint32_t*>(&h);
}

// ---------------------------------------------------------------- pre-pass
// z=0: gA0/gA1[r][k] = hi/lo bf16 of (k>=r ? A[r][k] : 0)   (row-major copy)
// z=1: gB0/gB1[c][k] = hi/lo bf16 of (k<=c ? B[k][c] : 0)   (transpose)
// Regions never read by the main kernel are skipped entirely.
__global__ __launch_bounds__(256)
void split_ab_kernel(const float* __restrict__ A, const float* __restrict__ B) {
    const int tid = threadIdx.x;

    if (blockIdx.z == 0) {
        const int rb = blockIdx.y * 64, kb = blockIdx.x * 64;
        if (kb < (rb & ~127)) return;            // k < row0 of main tile: unread
        const int r = rb + (tid >> 2);
        const int k0 = kb + (tid & 3) * 16;
        uint32_t hw[8], lw[8];
        if (kb + 63 < rb) {                       // read, but fully masked
            #pragma unroll
            for (int i = 0; i < 8; ++i) { hw[i] = 0u; lw[i] = 0u; }
        } else {
            #pragma unroll
            for (int q = 0; q < 4; ++q) {
                float4 v = *reinterpret_cast<const float4*>(
                    A + (size_t)r * NMAT + k0 + q * 4);
                const int kg = k0 + q * 4;
                float x0 = (kg + 0 >= r) ? v.x : 0.f;
                float x1 = (kg + 1 >= r) ? v.y : 0.f;
                float x2 = (kg + 2 >= r) ? v.z : 0.f;
                float x3 = (kg + 3 >= r) ? v.w : 0.f;
                float h0 = __bfloat162float(__float2bfloat16(x0));
                float h1 = __bfloat162float(__float2bfloat16(x1));
                float h2 = __bfloat162float(__float2bfloat16(x2));
                float h3 = __bfloat162float(__float2bfloat16(x3));
                hw[2 * q + 0] = pack_bf16x2(x0, x1);
                hw[2 * q + 1] = pack_bf16x2(x2, x3);
                lw[2 * q + 0] = pack_bf16x2(x0 - h0, x1 - h1);
                lw[2 * q + 1] = pack_bf16x2(x2 - h2, x3 - h3);
            }
        }
        uint4* p0 = reinterpret_cast<uint4*>(gA0 + (size_t)r * NMAT + k0);
        uint4* p1 = reinterpret_cast<uint4*>(gA1 + (size_t)r * NMAT + k0);
        p0[0] = make_uint4(hw[0], hw[1], hw[2], hw[3]);
        p0[1] = make_uint4(hw[4], hw[5], hw[6], hw[7]);
        p1[0] = make_uint4(lw[0], lw[1], lw[2], lw[3]);
        p1[1] = make_uint4(lw[4], lw[5], lw[6], lw[7]);
        return;
    }

    // ---- B branch: transpose + mask + split, 64x64 tile staged in smem ----
    const int kb = blockIdx.y * 64, cb = blockIdx.x * 64;
    if (kb >= (cb & ~255) + 256) return;          // k > col0+255: unread
    if (kb > cb + 63) {                           // read, but fully masked
        const uint4 z = make_uint4(0, 0, 0, 0);
        int u = tid * 2;
        int c = u >> 3, s = u & 7;
        uint4* p0 = reinterpret_cast<uint4*>(gB0 + (size_t)(cb + c) * NMAT + kb + s * 8);
        uint4* p1 = reinterpret_cast<uint4*>(gB1 + (size_t)(cb + c) * NMAT + kb + s * 8);
        p0[0] = z; p0[1] = z;
        p1[0] = z; p1[1] = z;
        return;
    }

    __shared__ float s[64][65];
    #pragma unroll
    for (int i = 0; i < 4; ++i) {
        int idx = tid + i * 256;
        int k = idx >> 4, cq = (idx & 15) * 4;
        float4 v = *reinterpret_cast<const float4*>(B + (size_t)(kb + k) * NMAT + cb + cq);
        int kg = kb + k;
        s[k][cq + 0] = (kg <= cb + cq + 0) ? v.x : 0.f;
        s[k][cq + 1] = (kg <= cb + cq + 1) ? v.y : 0.f;
        s[k][cq + 2] = (kg <= cb + cq + 2) ? v.z : 0.f;
        s[k][cq + 3] = (kg <= cb + cq + 3) ? v.w : 0.f;
    }
    __syncthreads();

    const int c = tid >> 2;
    const int ks = (tid & 3) * 16;
    float f[16];
    #pragma unroll
    for (int j = 0; j < 16; ++j) f[j] = s[ks + j][c];
    uint32_t h[8], l[8];
    #pragma unroll
    for (int j = 0; j < 8; ++j) {
        float x0 = f[2 * j], x1 = f[2 * j + 1];
        float h0 = __bfloat162float(__float2bfloat16(x0));
        float h1 = __bfloat162float(__float2bfloat16(x1));
        h[j] = pack_bf16x2(x0, x1);
        l[j] = pack_bf16x2(x0 - h0, x1 - h1);
    }
    uint4* p0 = reinterpret_cast<uint4*>(gB0 + (size_t)(cb + c) * NMAT + kb + ks);
    uint4* p1 = reinterpret_cast<uint4*>(gB1 + (size_t)(cb + c) * NMAT + kb + ks);
    p0[0] = make_uint4(h[0], h[1], h[2], h[3]);
    p0[1] = make_uint4(h[4], h[5], h[6], h[7]);
    p1[0] = make_uint4(l[0], l[1], l[2], l[3]);
    p1[1] = make_uint4(l[4], l[5], l[6], l[7]);
}

// ---------------------------------------------------------------- main GEMM
// smem: ctrl @ +0 (tmemptr @0, mbar[s] @8+8s); STAGES x 48KB buffers @ +1024.
constexpr int OFF_A0 = 0;
constexpr int OFF_A1 = 8192;
constexpr int OFF_B0 = 16384;
constexpr int OFF_B1 = 32768;
constexpr int STAGE_SZ = 49152;
constexpr int SMEM_NEED = 1024 + STAGES * STAGE_SZ + 1024;

#if defined(__CUDA_ARCH_FEAT_SM103_ALL) || !defined(__CUDA_ARCH__)
__device__ __forceinline__ void issue_chunk(uint32_t bb, int row0, int col0,
                                            int kt, int tid) {
    #pragma unroll
    for (int j = 0; j < 2; ++j) {
        int idx = tid + j * THREADS;           // A: 512 segs each
        int m = idx >> 2, seg = idx & 3;
        uint32_t off = m * 64 + seg * 16;
        off ^= (off >> 3) & 0x30;              // SW64
        const __nv_bfloat16* s0 = gA0 + (size_t)(row0 + m) * NMAT + kt + seg * 8;
        const __nv_bfloat16* s1 = gA1 + (size_t)(row0 + m) * NMAT + kt + seg * 8;
        cp_async16(bb + OFF_A0 + off, s0);
        cp_async16(bb + OFF_A1 + off, s1);
    }
    #pragma unroll
    for (int j = 0; j < 4; ++j) {
        int idx = tid + j * THREADS;           // B: 1024 segs each
        int crow = idx >> 2, seg = idx & 3;
        uint32_t off = crow * 64 + seg * 16;
        off ^= (off >> 3) & 0x30;              // SW64
        const __nv_bfloat16* s0 = gB0 + (size_t)(col0 + crow) * NMAT + kt + seg * 8;
        const __nv_bfloat16* s1 = gB1 + (size_t)(col0 + crow) * NMAT + kt + seg * 8;
        cp_async16(bb + OFF_B0 + off, s0);
        cp_async16(bb + OFF_B1 + off, s1);
    }
}
#endif

__global__ __launch_bounds__(THREADS, 1)
void trimm_tc_kernel(const float* __restrict__ A,
                     const float* __restrict__ B,
                     float* __restrict__ C) {
    const int bid = blockIdx.x;
    const int tid = threadIdx.x;

    // ---- longest-k-first schedule decode ----
    // Compute tiles ordered by descending d = 2*bc2 - br (d = 30..-1);
    // zero tiles (br > 2*bc2+1) packed at the end.
    int br, bc2;
    bool zero_tile = (bid >= NCOMPUTE);
    if (zero_tile) {
        int z = bid - NCOMPUTE;
        int b2 = 0;
        for (;; ++b2) { int cnt = 30 - 2 * b2; if (z < cnt) break; z -= cnt; }
        bc2 = b2; br = 2 * b2 + 2 + z;
    } else {
        int rem = bid, d = 30;
        for (;; --d) {
            int cnt = (d >= 0) ? (16 - ((d + 1) >> 1)) : 16;
            if (rem < cnt) break;
            rem -= cnt;
        }
        int lo = (d >= 0) ? ((d + 1) >> 1) : 0;
        bc2 = lo + rem; br = 2 * bc2 - d;
    }
    const int row0 = br * BM, col0 = bc2 * BN;

    if (zero_tile) {
        const float4 z4 = make_float4(0.f, 0.f, 0.f, 0.f);
        float4* out = reinterpret_cast<float4*>(C + (size_t)row0 * NMAT + col0);
        #pragma unroll
        for (int i = 0; i < (BM * BN / 4) / THREADS; ++i) {
            int idx = tid + i * THREADS;
            out[(size_t)(idx >> 6) * (NMAT / 4) + (idx & 63)] = z4;
        }
        return;
    }

    const int nch = (col0 + BN - row0) / KC;     // 4..128, divisible by 4

#if defined(__CUDA_ARCH__) && !defined(__CUDA_ARCH_FEAT_SM103_ALL)
    // ---------------- arch-generic fallback: SIMT fp32, two 128-col halves --
    constexpr int BK = 8, TM = 8, TN = 8;
    __shared__ float As[BK][128 + 4];
    __shared__ float Bs[BK][128];

    const int ty = tid >> 4, tx = tid & 15;
    const int a_row = tid >> 1, a_k = (tid & 1) * 4;
    const int b_k = tid >> 5, b_col = (tid & 31) * 4;
    const int arow_g = row0 + a_row;

    for (int h = 0; h < 2; ++h) {
        const int col0h = col0 + h * 128;
        if (row0 > col0h + 127) {
            const float4 z4 = make_float4(0.f, 0.f, 0.f, 0.f);
            float4* out = reinterpret_cast<float4*>(C + (size_t)row0 * NMAT + col0h);
            #pragma unroll
            for (int i = 0; i < (BM * 128 / 4) / THREADS; ++i) {
                int idx = tid + i * THREADS;
                out[(size_t)(idx >> 5) * (NMAT / 4) + (idx & 31)] = z4;
            }
            continue;
        }
        float acc[TM][TN];
        #pragma unroll
        for (int i = 0; i < TM; ++i)
            #pragma unroll
            for (int j = 0; j < TN; ++j) acc[i][j] = 0.f;
        const int cg = col0h + b_col;
        __syncthreads();
        for (int kt = row0; kt < col0h + 128; kt += BK) {
            {
                const float4 av = *reinterpret_cast<const float4*>(
                    A + (size_t)arow_g * NMAT + (kt + a_k));
                const int kg = kt + a_k;
                As[a_k + 0][a_row] = (kg + 0 >= arow_g) ? av.x : 0.f;
                As[a_k + 1][a_row] = (kg + 1 >= arow_g) ? av.y : 0.f;
                As[a_k + 2][a_row] = (kg + 2 >= arow_g) ? av.z : 0.f;
                As[a_k + 3][a_row] = (kg + 3 >= arow_g) ? av.w : 0.f;
            }
            {
                const int bkg = kt + b_k;
                float4 bv = *reinterpret_cast<const float4*>(B + (size_t)bkg * NMAT + cg);
                bv.x = (bkg <= cg + 0) ? bv.x : 0.f;
                bv.y = (bkg <= cg + 1) ? bv.y : 0.f;
                bv.z = (bkg <= cg + 2) ? bv.z : 0.f;
                bv.w = (bkg <= cg + 3) ? bv.w : 0.f;
                *reinterpret_cast<float4*>(&Bs[b_k][b_col]) = bv;
            }
            __syncthreads();
            #pragma unroll
            for (int kk = 0; kk < BK; ++kk) {
                float ar[TM], bb[TN];
                #pragma unroll
                for (int i = 0; i < TM; ++i) ar[i] = As[kk][ty * TM + i];
                #pragma unroll
                for (int j = 0; j < TN; ++j) bb[j] = Bs[kk][tx * TN + j];
                #pragma unroll
                for (int i = 0; i < TM; ++i)
                    #pragma unroll
                    for (int j = 0; j < TN; ++j)
                        acc[i][j] = fmaf(ar[i], bb[j], acc[i][j]);
            }
            __syncthreads();
        }
        #pragma unroll
        for (int i = 0; i < TM; ++i) {
            float4* crow = reinterpret_cast<float4*>(
                C + (size_t)(row0 + ty * TM + i) * NMAT + col0h + tx * TN);
            crow[0] = make_float4(acc[i][0], acc[i][1], acc[i][2], acc[i][3]);
            crow[1] = make_float4(acc[i][4], acc[i][5], acc[i][6], acc[i][7]);
        }
    }
#else
    // ---------------- sm_103a fast path: 4-stage cp.async -> tcgen05 --------
    const int wid = tid >> 5, lid = tid & 31;

    extern __shared__ char dsm[];
    const uint32_t raw = smem_u32(dsm);
    const uint32_t sb = (raw + 1023u) & ~1023u;
    const uint32_t s_tmemptr = sb;
    const uint32_t s_mbar = sb + 8;

    if (wid == 0) { TC_ALLOC(s_tmemptr, 256); TC_RELINQ(); }
    if (tid == 0) {
        #pragma unroll
        for (int s = 0; s < STAGES; ++s) MBAR_INIT(s_mbar + 8 * s, 1);
    }
    __syncthreads();
    uint32_t tmem;
    asm volatile("ld.shared.b32 %0, [%1];" : "=r"(tmem) : "r"(s_tmemptr));

    const bool lead = (wid == 0) ? (elect_one() != 0) : false;

    // idesc kind::f16: dtype=F32, a/btype=BF16, N=256, M=128
    const uint32_t idesc = (1u << 4) | (1u << 7) | (1u << 10)
                         | ((BN / 8) << 17) | ((BM / 16) << 24);

    // prologue: fill stages 0..2 (nch >= 4 always)
    #pragma unroll
    for (int s = 0; s < 3; ++s) {
        issue_chunk(sb + 1024 + s * STAGE_SZ, row0, col0, row0 + s * KC, tid);
        CP_COMMIT();
    }

    for (int c = 0; c < nch; ++c) {
        const int slot = c & 3;
        const uint32_t bb = sb + 1024 + slot * STAGE_SZ;

        const int rem = nch - 1 - c;
        if (rem >= 2) { CP_WAIT2(); } else if (rem == 1) { CP_WAIT1(); } else { CP_WAIT0(); }
        __syncthreads();

        if (lead) {
            FENCE_ASYNC();
            const uint64_t dA0 = mk_desc64(bb + OFF_A0);
            const uint64_t dA1 = mk_desc64(bb + OFF_A1);
            const uint64_t dB0 = mk_desc64(bb + OFF_B0);
            const uint64_t dB1 = mk_desc64(bb + OFF_B1);
            #pragma unroll
            for (int s = 0; s < 2; ++s) {
                mma_f16_ss(tmem, dA0 + 2 * s, dB0 + 2 * s, idesc,
                           (c > 0 || s > 0) ? 1u : 0u);
                mma_f16_ss(tmem, dA0 + 2 * s, dB1 + 2 * s, idesc, 1u);
                mma_f16_ss(tmem, dA1 + 2 * s, dB0 + 2 * s, idesc, 1u);
            }
            TC_COMMIT(s_mbar + 8 * slot);
        }

        if (c + 3 < nch) {
            if (c >= 1) MBAR_WAIT_PARITY(s_mbar + 8 * ((c - 1) & 3), ((c - 1) >> 2) & 1);
            issue_chunk(sb + 1024 + ((c + 3) & 3) * STAGE_SZ, row0, col0,
                        row0 + (c + 3) * KC, tid);
            CP_COMMIT();
        }
    }

    {
        const int L = nch - 1;
        MBAR_WAIT_PARITY(s_mbar + 8 * (L & 3), (L >> 2) & 1);
    }
    TC_FENCE_AFTER();

    // epilogue: 8 warps; warp w covers rows (w&3)*32+lid, col half=(w>>2)*128
    {
        const int wsub = wid & 3, half = wid >> 2;
        const int r = row0 + wsub * 32 + lid;
        #pragma unroll
        for (int batch = 0; batch < 4; ++batch) {
            uint32_t rg[32];
            LDTM_X32(rg, tmem + half * 128 + batch * 32);
            TC_WAIT_LD();
            float4* dst = reinterpret_cast<float4*>(
                C + (size_t)r * NMAT + col0 + half * 128 + batch * 32);
            #pragma unroll
            for (int q = 0; q < 8; ++q)
                dst[q] = make_float4(__uint_as_float(rg[4 * q + 0]),
                                     __uint_as_float(rg[4 * q + 1]),
                                     __uint_as_float(rg[4 * q + 2]),
                                     __uint_as_float(rg[4 * q + 3]));
        }
        TC_FENCE_BEFORE();
    }
    __syncthreads();
    if (wid == 0) { TC_DEALLOC(tmem, 256); }
#endif
}

// ---------------------------------------------------------------- launch
extern "C" void kernel_launch(void* const* d_in, const int* in_sizes, int n_in,
                              void* d_out, int out_size) {
    const float* A = (const float*)d_in[0];
    const float* B = (const float*)d_in[1];
    float* C = (float*)d_out;

    cudaFuncSetAttribute(trimm_tc_kernel,
                         cudaFuncAttributeMaxDynamicSharedMemorySize, SMEM_NEED);

    split_ab_kernel<<<dim3(NMAT / 64, NMAT / 64, 2), 256>>>(A, B);
    trimm_tc_kernel<<<NTILES, THREADS, SMEM_NEED>>>(A, B, C);
}

// round 10
// speedup vs baseline: 1.5179x; 1.0133x over previous
#include <cuda_runtime.h>
#include <cuda_bf16.h>
#include <cstdint>

// C = triu(triu(A) @ triu(B)), N = 4096, fp32.
// sm_103a path: A,B pre-split into masked bf16 hi/lo (B transposed K-major);
// main kernel: warp-specialized pipeline — 8 producer warps (cp.async) +
// 1 MMA warp, per-stage full/empty mbarriers, NO syncthreads in the loop.
// 4 stages, KC=32 (SW64 64B rows), 3 bf16 MMAs per K16 (h*h + h*l + l*h),
// fp32 accum in TMEM, 128x256 tiles, longest-k-first 1D tile schedule.
// Fallback (arch-generic PTX): SIMT fp32 kernel with the same mapping.

constexpr int NMAT = 4096;
constexpr int BM = 128;
constexpr int BN = 256;
constexpr int KC = 32;         // k-chunk (32 bf16 = 64B rows, SW64 native)
constexpr int THREADS = 288;   // 8 producer warps (256) + 1 MMA warp
constexpr int PROD = 256;      // producer thread count
constexpr int STAGES = 4;
constexpr int NTILES = 512;    // 32 x 16
constexpr int NCOMPUTE = 272;  // tiles with row0 <= col0+BN-1

// Scratch: masked splits. gA0/gA1: A [r][k]. gB0/gB1: B^T [c][k]. All K-major.
__device__ __align__(1024) __nv_bfloat16 gA0[(size_t)NMAT * NMAT];
__device__ __align__(1024) __nv_bfloat16 gA1[(size_t)NMAT * NMAT];
__device__ __align__(1024) __nv_bfloat16 gB0[(size_t)NMAT * NMAT];
__device__ __align__(1024) __nv_bfloat16 gB1[(size_t)NMAT * NMAT];

// ---------------------------------------------------------------- helpers
__device__ __forceinline__ uint32_t smem_u32(const void* p) {
    uint32_t a;
    asm("{ .reg .u64 t; cvta.to.shared.u64 t, %1; cvt.u32.u64 %0, t; }"
        : "=r"(a) : "l"(p));
    return a;
}

#if defined(__CUDA_ARCH_FEAT_SM103_ALL) || !defined(__CUDA_ARCH__)
__device__ __forceinline__ void mma_f16_ss(uint32_t d, uint64_t ad, uint64_t bd,
                                           uint32_t idesc, uint32_t en) {
    asm volatile(
        "{\n\t.reg .pred p;\n\tsetp.ne.u32 p, %5, 0;\n\t"
        "tcgen05.mma.cta_group::1.kind::f16 [%0], %1, %2, %3, {%4,%4,%4,%4}, p;\n\t}"
        :: "r"(d), "l"(ad), "l"(bd), "r"(idesc), "r"(0u), "r"(en) : "memory");
}
__device__ __forceinline__ void cp_async16(uint32_t dst, const void* src) {
    asm volatile("cp.async.cg.shared.global [%0], [%1], 16;"
                 :: "r"(dst), "l"(src) : "memory");
}
#define CP_COMMIT()      asm volatile("cp.async.commit_group;" ::: "memory")
#define CP_WAIT0()       asm volatile("cp.async.wait_group 0;" ::: "memory")
#define CP_WAIT1()       asm volatile("cp.async.wait_group 1;" ::: "memory")
#define CP_WAIT2()       asm volatile("cp.async.wait_group 2;" ::: "memory")
#define TC_ALLOC(sl, n)  asm volatile("tcgen05.alloc.cta_group::1.sync.aligned.shared::cta.b32 [%0], %1;" :: "r"(sl), "r"((uint32_t)(n)) : "memory")
#define TC_RELINQ()      asm volatile("tcgen05.relinquish_alloc_permit.cta_group::1.sync.aligned;")
#define TC_DEALLOC(t, n) asm volatile("tcgen05.dealloc.cta_group::1.sync.aligned.b32 %0, %1;" :: "r"(t), "r"((uint32_t)(n)))
#define TC_COMMIT(mb)    asm volatile("tcgen05.commit.cta_group::1.mbarrier::arrive::one.shared::cluster.b64 [%0];" :: "r"(mb) : "memory")
#define TC_FENCE_AFTER() asm volatile("tcgen05.fence::after_thread_sync;" ::: "memory")
#define TC_FENCE_BEFORE() asm volatile("tcgen05.fence::before_thread_sync;" ::: "memory")
#define TC_WAIT_LD()     asm volatile("tcgen05.wait::ld.sync.aligned;" ::: "memory")
#define FENCE_ASYNC()    asm volatile("fence.proxy.async.shared::cta;" ::: "memory")
#define MBAR_INIT(mb, c) asm volatile("mbarrier.init.shared.b64 [%0], %1;" :: "r"(mb), "r"((uint32_t)(c)) : "memory")
#define MBAR_ARRIVE(mb)  asm volatile("mbarrier.arrive.shared.b64 _, [%0];" :: "r"(mb) : "memory")

#define MBAR_WAIT_PARITY(mb, ph) do {                                           \
    uint32_t _m = (mb), _p = (ph), _d;                                          \
    asm volatile("{\n\t.reg .pred p;\n\t"                                       \
        "mbarrier.try_wait.parity.acquire.cta.shared::cta.b64 p, [%1], %2;\n\t" \
        "selp.b32 %0, 1, 0, p;\n\t}" : "=r"(_d) : "r"(_m), "r"(_p) : "memory"); \
    if (!_d) {                                                                  \
        asm volatile("{\n\t.reg .pred P1;\n\t"                                  \
        "WL_%=:\n\t"                                                            \
        "mbarrier.try_wait.parity.acquire.cta.shared::cta.b64 P1, [%0], %1, 0x989680;\n\t" \
        "@P1 bra.uni WD_%=;\n\t"                                                \
        "bra.uni WL_%=;\n\t"                                                    \
        "WD_%=:\n\t}" :: "r"(_m), "r"(_p) : "memory");                          \
    }                                                                           \
} while (0)

#define LDTM_X32(r, a)                                                          \
    asm volatile("tcgen05.ld.sync.aligned.32x32b.x32.b32 "                      \
        "{%0, %1, %2, %3, %4, %5, %6, %7, %8, %9, %10, %11, %12, %13, %14, %15,"\
        " %16, %17, %18, %19, %20, %21, %22, %23, %24, %25, %26, %27, %28, %29, %30, %31}, [%32];" \
        : "=r"((r)[0]), "=r"((r)[1]), "=r"((r)[2]), "=r"((r)[3]),               \
          "=r"((r)[4]), "=r"((r)[5]), "=r"((r)[6]), "=r"((r)[7]),               \
          "=r"((r)[8]), "=r"((r)[9]), "=r"((r)[10]), "=r"((r)[11]),             \
          "=r"((r)[12]), "=r"((r)[13]), "=r"((r)[14]), "=r"((r)[15]),           \
          "=r"((r)[16]), "=r"((r)[17]), "=r"((r)[18]), "=r"((r)[19]),           \
          "=r"((r)[20]), "=r"((r)[21]), "=r"((r)[22]), "=r"((r)[23]),           \
          "=r"((r)[24]), "=r"((r)[25]), "=r"((r)[26]), "=r"((r)[27]),           \
          "=r"((r)[28]), "=r"((r)[29]), "=r"((r)[30]), "=r"((r)[31])            \
        : "r"(a))
#endif  // tcgen05 helpers

// SW64 smem descriptor (K-major, 64B rows): layout=SW64(4), ver=1, SBO=32, LBO=1
constexpr uint64_t DESC_BASE_SW64 =
    (uint64_t(4) << 61) | (uint64_t(1) << 46) | (uint64_t(32) << 32) | (uint64_t(1) << 16);
__device__ __forceinline__ uint64_t mk_desc64(uint32_t a) {
    return DESC_BASE_SW64 | ((uint64_t)(a >> 4) & 0x3FFF);
}

__device__ __forceinline__ uint32_t pack_bf16x2(float a, float b) {
    __nv_bfloat162 h = __halves2bfloat162(__float2bfloat16(a), __float2bfloat16(b));
    return *reinterpret_cast<uint32_t*>(&h);
}

// ---------------------------------------------------------------- pre-pass
// z=0: gA0/gA1[r][k] = hi/lo bf16 of (k>=r ? A[r][k] : 0)   (row-major copy)
// z=1: gB0/gB1[c][k] = hi/lo bf16 of (k<=c ? B[k][c] : 0)   (transpose)
// Regions never read by the main kernel are skipped entirely.
__global__ __launch_bounds__(256)
void split_ab_kernel(const float* __restrict__ A, const float* __restrict__ B) {
    const int tid = threadIdx.x;

    if (blockIdx.z == 0) {
        const int rb = blockIdx.y * 64, kb = blockIdx.x * 64;
        if (kb < (rb & ~127)) return;            // k < row0 of main tile: unread
        const int r = rb + (tid >> 2);
        const int k0 = kb + (tid & 3) * 16;
        uint32_t hw[8], lw[8];
        if (kb + 63 < rb) {                       // read, but fully masked
            #pragma unroll
            for (int i = 0; i < 8; ++i) { hw[i] = 0u; lw[i] = 0u; }
        } else {
            #pragma unroll
            for (int q = 0; q < 4; ++q) {
                float4 v = *reinterpret_cast<const float4*>(
                    A + (size_t)r * NMAT + k0 + q * 4);
                const int kg = k0 + q * 4;
                float x0 = (kg + 0 >= r) ? v.x : 0.f;
                float x1 = (kg + 1 >= r) ? v.y : 0.f;
                float x2 = (kg + 2 >= r) ? v.z : 0.f;
                float x3 = (kg + 3 >= r) ? v.w : 0.f;
                float h0 = __bfloat162float(__float2bfloat16(x0));
                float h1 = __bfloat162float(__float2bfloat16(x1));
                float h2 = __bfloat162float(__float2bfloat16(x2));
                float h3 = __bfloat162float(__float2bfloat16(x3));
                hw[2 * q + 0] = pack_bf16x2(x0, x1);
                hw[2 * q + 1] = pack_bf16x2(x2, x3);
                lw[2 * q + 0] = pack_bf16x2(x0 - h0, x1 - h1);
                lw[2 * q + 1] = pack_bf16x2(x2 - h2, x3 - h3);
            }
        }
        uint4* p0 = reinterpret_cast<uint4*>(gA0 + (size_t)r * NMAT + k0);
        uint4* p1 = reinterpret_cast<uint4*>(gA1 + (size_t)r * NMAT + k0);
        p0[0] = make_uint4(hw[0], hw[1], hw[2], hw[3]);
        p0[1] = make_uint4(hw[4], hw[5], hw[6], hw[7]);
        p1[0] = make_uint4(lw[0], lw[1], lw[2], lw[3]);
        p1[1] = make_uint4(lw[4], lw[5], lw[6], lw[7]);
        return;
    }

    // ---- B branch: transpose + mask + split, 64x64 tile staged in smem ----
    const int kb = blockIdx.y * 64, cb = blockIdx.x * 64;
    if (kb >= (cb & ~255) + 256) return;          // k > col0+255: unread
    if (kb > cb + 63) {                           // read, but fully masked
        const uint4 z = make_uint4(0, 0, 0, 0);
        int u = tid * 2;
        int c = u >> 3, s = u & 7;
        uint4* p0 = reinterpret_cast<uint4*>(gB0 + (size_t)(cb + c) * NMAT + kb + s * 8);
        uint4* p1 = reinterpret_cast<uint4*>(gB1 + (size_t)(cb + c) * NMAT + kb + s * 8);
        p0[0] = z; p0[1] = z;
        p1[0] = z; p1[1] = z;
        return;
    }

    __shared__ float s[64][65];
    #pragma unroll
    for (int i = 0; i < 4; ++i) {
        int idx = tid + i * 256;
        int k = idx >> 4, cq = (idx & 15) * 4;
        float4 v = *reinterpret_cast<const float4*>(B + (size_t)(kb + k) * NMAT + cb + cq);
        int kg = kb + k;
        s[k][cq + 0] = (kg <= cb + cq + 0) ? v.x : 0.f;
        s[k][cq + 1] = (kg <= cb + cq + 1) ? v.y : 0.f;
        s[k][cq + 2] = (kg <= cb + cq + 2) ? v.z : 0.f;
        s[k][cq + 3] = (kg <= cb + cq + 3) ? v.w : 0.f;
    }
    __syncthreads();

    const int c = tid >> 2;
    const int ks = (tid & 3) * 16;
    float f[16];
    #pragma unroll
    for (int j = 0; j < 16; ++j) f[j] = s[ks + j][c];
    uint32_t h[8], l[8];
    #pragma unroll
    for (int j = 0; j < 8; ++j) {
        float x0 = f[2 * j], x1 = f[2 * j + 1];
        float h0 = __bfloat162float(__float2bfloat16(x0));
        float h1 = __bfloat162float(__float2bfloat16(x1));
        h[j] = pack_bf16x2(x0, x1);
        l[j] = pack_bf16x2(x0 - h0, x1 - h1);
    }
    uint4* p0 = reinterpret_cast<uint4*>(gB0 + (size_t)(cb + c) * NMAT + kb + ks);
    uint4* p1 = reinterpret_cast<uint4*>(gB1 + (size_t)(cb + c) * NMAT + kb + ks);
    p0[0] = make_uint4(h[0], h[1], h[2], h[3]);
    p0[1] = make_uint4(h[4], h[5], h[6], h[7]);
    p1[0] = make_uint4(l[0], l[1], l[2], l[3]);
    p1[1] = make_uint4(l[4], l[5], l[6], l[7]);
}

// ---------------------------------------------------------------- main GEMM
// smem: ctrl @ +0 (tmemptr @0, full[s] @8+8s, empty[s] @40+8s, done @72);
// STAGES x 48KB buffers @ +1024.
constexpr int OFF_A0 = 0;
constexpr int OFF_A1 = 8192;
constexpr int OFF_B0 = 16384;
constexpr int OFF_B1 = 32768;
constexpr int STAGE_SZ = 49152;
constexpr int SMEM_NEED = 1024 + STAGES * STAGE_SZ + 1024;

#if defined(__CUDA_ARCH_FEAT_SM103_ALL) || !defined(__CUDA_ARCH__)
__device__ __forceinline__ void issue_chunk(uint32_t bb, int row0, int col0,
                                            int kt, int tid) {
    #pragma unroll
    for (int j = 0; j < 2; ++j) {
        int idx = tid + j * PROD;              // A: 512 segs each
        int m = idx >> 2, seg = idx & 3;
        uint32_t off = m * 64 + seg * 16;
        off ^= (off >> 3) & 0x30;              // SW64
        const __nv_bfloat16* s0 = gA0 + (size_t)(row0 + m) * NMAT + kt + seg * 8;
        const __nv_bfloat16* s1 = gA1 + (size_t)(row0 + m) * NMAT + kt + seg * 8;
        cp_async16(bb + OFF_A0 + off, s0);
        cp_async16(bb + OFF_A1 + off, s1);
    }
    #pragma unroll
    for (int j = 0; j < 4; ++j) {
        int idx = tid + j * PROD;              // B: 1024 segs each
        int crow = idx >> 2, seg = idx & 3;
        uint32_t off = crow * 64 + seg * 16;
        off ^= (off >> 3) & 0x30;              // SW64
        const __nv_bfloat16* s0 = gB0 + (size_t)(col0 + crow) * NMAT + kt + seg * 8;
        const __nv_bfloat16* s1 = gB1 + (size_t)(col0 + crow) * NMAT + kt + seg * 8;
        cp_async16(bb + OFF_B0 + off, s0);
        cp_async16(bb + OFF_B1 + off, s1);
    }
}
#endif

__global__ __launch_bounds__(THREADS, 1)
void trimm_tc_kernel(const float* __restrict__ A,
                     const float* __restrict__ B,
                     float* __restrict__ C) {
    const int bid = blockIdx.x;
    const int tid = threadIdx.x;

    // ---- longest-k-first schedule decode ----
    int br, bc2;
    bool zero_tile = (bid >= NCOMPUTE);
    if (zero_tile) {
        int z = bid - NCOMPUTE;
        int b2 = 0;
        for (;; ++b2) { int cnt = 30 - 2 * b2; if (z < cnt) break; z -= cnt; }
        bc2 = b2; br = 2 * b2 + 2 + z;
    } else {
        int rem = bid, d = 30;
        for (;; --d) {
            int cnt = (d >= 0) ? (16 - ((d + 1) >> 1)) : 16;
            if (rem < cnt) break;
            rem -= cnt;
        }
        int lo = (d >= 0) ? ((d + 1) >> 1) : 0;
        bc2 = lo + rem; br = 2 * bc2 - d;
    }
    const int row0 = br * BM, col0 = bc2 * BN;

    if (zero_tile) {
        const float4 z4 = make_float4(0.f, 0.f, 0.f, 0.f);
        float4* out = reinterpret_cast<float4*>(C + (size_t)row0 * NMAT + col0);
        for (int idx = tid; idx < BM * BN / 4; idx += THREADS)
            out[(size_t)(idx >> 6) * (NMAT / 4) + (idx & 63)] = z4;
        return;
    }

    const int nch = (col0 + BN - row0) / KC;     // 4..128, divisible by 4

#if defined(__CUDA_ARCH__) && !defined(__CUDA_ARCH_FEAT_SM103_ALL)
    // ---------------- arch-generic fallback: SIMT fp32, two 128-col halves --
    constexpr int BK = 8, TM = 8, TN = 8;
    __shared__ float As[BK][128 + 4];
    __shared__ float Bs[BK][128];

    const bool act = (tid < 256);
    const int ty = tid >> 4, tx = tid & 15;
    const int a_row = tid >> 1, a_k = (tid & 1) * 4;
    const int b_k = (tid >> 5) & 7, b_col = (tid & 31) * 4;
    const int arow_g = row0 + (act ? a_row : 0);

    for (int h = 0; h < 2; ++h) {
        const int col0h = col0 + h * 128;
        if (row0 > col0h + 127) {
            const float4 z4 = make_float4(0.f, 0.f, 0.f, 0.f);
            float4* out = reinterpret_cast<float4*>(C + (size_t)row0 * NMAT + col0h);
            for (int idx = tid; idx < BM * 128 / 4; idx += THREADS)
                out[(size_t)(idx >> 5) * (NMAT / 4) + (idx & 31)] = z4;
            continue;
        }
        float acc[TM][TN];
        #pragma unroll
        for (int i = 0; i < TM; ++i)
            #pragma unroll
            for (int j = 0; j < TN; ++j) acc[i][j] = 0.f;
        const int cg = col0h + b_col;
        __syncthreads();
        for (int kt = row0; kt < col0h + 128; kt += BK) {
            if (act) {
                const float4 av = *reinterpret_cast<const float4*>(
                    A + (size_t)arow_g * NMAT + (kt + a_k));
                const int kg = kt + a_k;
                As[a_k + 0][a_row] = (kg + 0 >= arow_g) ? av.x : 0.f;
                As[a_k + 1][a_row] = (kg + 1 >= arow_g) ? av.y : 0.f;
                As[a_k + 2][a_row] = (kg + 2 >= arow_g) ? av.z : 0.f;
                As[a_k + 3][a_row] = (kg + 3 >= arow_g) ? av.w : 0.f;
                const int bkg = kt + b_k;
                float4 bv = *reinterpret_cast<const float4*>(B + (size_t)bkg * NMAT + cg);
                bv.x = (bkg <= cg + 0) ? bv.x : 0.f;
                bv.y = (bkg <= cg + 1) ? bv.y : 0.f;
                bv.z = (bkg <= cg + 2) ? bv.z : 0.f;
                bv.w = (bkg <= cg + 3) ? bv.w : 0.f;
                *reinterpret_cast<float4*>(&Bs[b_k][b_col]) = bv;
            }
            __syncthreads();
            if (act) {
                #pragma unroll
                for (int kk = 0; kk < BK; ++kk) {
                    float ar[TM], bb[TN];
                    #pragma unroll
                    for (int i = 0; i < TM; ++i) ar[i] = As[kk][ty * TM + i];
                    #pragma unroll
                    for (int j = 0; j < TN; ++j) bb[j] = Bs[kk][tx * TN + j];
                    #pragma unroll
                    for (int i = 0; i < TM; ++i)
                        #pragma unroll
                        for (int j = 0; j < TN; ++j)
                            acc[i][j] = fmaf(ar[i], bb[j], acc[i][j]);
                }
            }
            __syncthreads();
        }
        if (act) {
            #pragma unroll
            for (int i = 0; i < TM; ++i) {
                float4* crow = reinterpret_cast<float4*>(
                    C + (size_t)(row0 + ty * TM + i) * NMAT + col0h + tx * TN);
                crow[0] = make_float4(acc[i][0], acc[i][1], acc[i][2], acc[i][3]);
                crow[1] = make_float4(acc[i][4], acc[i][5], acc[i][6], acc[i][7]);
            }
        }
    }
#else
    // ------------- sm_103a fast path: warp-specialized cp.async -> tcgen05 --
    const int wid = tid >> 5, lid = tid & 31;

    extern __shared__ char dsm[];
    const uint32_t raw = smem_u32(dsm);
    const uint32_t sb = (raw + 1023u) & ~1023u;
    const uint32_t s_tmemptr = sb;
    const uint32_t s_full  = sb + 8;            // full[s]  @ sb+8  .. +32
    const uint32_t s_empty = sb + 40;           // empty[s] @ sb+40 .. +64
    const uint32_t s_done  = sb + 72;

    if (wid == 0) { TC_ALLOC(s_tmemptr, 256); TC_RELINQ(); }
    if (tid == 0) {
        #pragma unroll
        for (int s = 0; s < STAGES; ++s) {
            MBAR_INIT(s_full + 8 * s, PROD);    // 256 producer arrivals
            MBAR_INIT(s_empty + 8 * s, 1);      // tcgen05.commit arrival
        }
        MBAR_INIT(s_done, 1);
    }
    __syncthreads();
    uint32_t tmem;
    asm volatile("ld.shared.b32 %0, [%1];" : "=r"(tmem) : "r"(s_tmemptr));

    // idesc kind::f16: dtype=F32, a/btype=BF16, N=256, M=128
    const uint32_t idesc = (1u << 4) | (1u << 7) | (1u << 10)
                         | ((BN / 8) << 17) | ((BM / 16) << 24);

    if (tid < PROD) {
        // ---------------- producers: warps 0-7 ----------------
        for (int i = 0; i < nch; ++i) {
            const int s = i & 3;
            if (i >= 4)  // stage s last used by chunk i-4; wait its MMA done
                MBAR_WAIT_PARITY(s_empty + 8 * s, ((i - 4) >> 2) & 1);
            issue_chunk(sb + 1024 + s * STAGE_SZ, row0, col0, row0 + i * KC, tid);
            CP_COMMIT();
            if (i >= 2) {            // group i-2 complete -> signal its stage
                CP_WAIT2();
                MBAR_ARRIVE(s_full + 8 * ((i - 2) & 3));
            }
        }
        CP_WAIT1();
        MBAR_ARRIVE(s_full + 8 * ((nch - 2) & 3));
        CP_WAIT0();
        MBAR_ARRIVE(s_full + 8 * ((nch - 1) & 3));
    } else {
        // ---------------- MMA warp: warp 8 ----------------
        for (int i = 0; i < nch; ++i) {
            const int s = i & 3;
            MBAR_WAIT_PARITY(s_full + 8 * s, (i >> 2) & 1);
            FENCE_ASYNC();
            if (lid == 0) {
                const uint32_t bb = sb + 1024 + s * STAGE_SZ;
                const uint64_t dA0 = mk_desc64(bb + OFF_A0);
                const uint64_t dA1 = mk_desc64(bb + OFF_A1);
                const uint64_t dB0 = mk_desc64(bb + OFF_B0);
                const uint64_t dB1 = mk_desc64(bb + OFF_B1);
                #pragma unroll
                for (int st = 0; st < 2; ++st) {
                    mma_f16_ss(tmem, dA0 + 2 * st, dB0 + 2 * st, idesc,
                               (i > 0 || st > 0) ? 1u : 0u);
                    mma_f16_ss(tmem, dA0 + 2 * st, dB1 + 2 * st, idesc, 1u);
                    mma_f16_ss(tmem, dA1 + 2 * st, dB0 + 2 * st, idesc, 1u);
                }
                TC_COMMIT(s_empty + 8 * s);     // MMA(i) done -> stage free
            }
            __syncwarp();
        }
        if (lid == 0) TC_COMMIT(s_done);        // all MMAs complete
        __syncwarp();
    }

    __syncthreads();
    MBAR_WAIT_PARITY(s_done, 0);
    TC_FENCE_AFTER();

    // epilogue: warps 0-7; warp w covers rows (w&3)*32+lid, half=(w>>2)*128
    if (wid < 8) {
        const int wsub = wid & 3, half = wid >> 2;
        const int r = row0 + wsub * 32 + lid;
        #pragma unroll
        for (int batch = 0; batch < 4; ++batch) {
            uint32_t rg[32];
            LDTM_X32(rg, tmem + half * 128 + batch * 32);
            TC_WAIT_LD();
            float4* dst = reinterpret_cast<float4*>(
                C + (size_t)r * NMAT + col0 + half * 128 + batch * 32);
            #pragma unroll
            for (int q = 0; q < 8; ++q)
                dst[q] = make_float4(__uint_as_float(rg[4 * q + 0]),
                                     __uint_as_float(rg[4 * q + 1]),
                                     __uint_as_float(rg[4 * q + 2]),
                                     __uint_as_float(rg[4 * q + 3]));
        }
        TC_FENCE_BEFORE();
    }
    __syncthreads();
    if (wid == 0) { TC_DEALLOC(tmem, 256); }
#endif
}

// ---------------------------------------------------------------- launch
extern "C" void kernel_launch(void* const* d_in, const int* in_sizes, int n_in,
                              void* d_out, int out_size) {
    const float* A = (const float*)d_in[0];
    const float* B = (const float*)d_in[1];
    float* C = (float*)d_out;

    cudaFuncSetAttribute(trimm_tc_kernel,
                         cudaFuncAttributeMaxDynamicSharedMemorySize, SMEM_NEED);

    split_ab_kernel<<<dim3(NMAT / 64, NMAT / 64, 2), 256>>>(A, B);
    trimm_tc_kernel<<<NTILES, THREADS, SMEM_NEED>>>(A, B, C);
}